// round 2
// baseline (speedup 1.0000x reference)
#include <cuda_runtime.h>

// LatentReverb: B=4, C=4, H=W=64, NREF=16
// DECAY=0.8, WET_MIX=0.3, FEEDBACK=0.4, ROOM=0.5, HEADS=4 (head_dim=1)

#define BB 4
#define CC 4
#define HH 64
#define WW 64
#define NPIX (BB*HH*WW)
#define LOG2E 1.4426950408889634f

// ---------------- scratch (static device globals; no allocation) -------------
__device__ float  g_fbA[BB*CC*HH*WW];
__device__ float  g_fbB[BB*CC*HH*WW];
__device__ float  g_wet[BB*CC*HH*WW];
__device__ float  g_q [16*4096];
__device__ float2 g_kv[16*4096];
__device__ float  g_o [16*4096];
__device__ float  g_wet3[BB*CC*HH*WW];

__device__ unsigned g_bar_arrive = 0;
__device__ unsigned g_bar_gen    = 0;

// ---------------- helpers ----------------------------------------------------
__device__ __forceinline__ float fexp2(float x) {
    float y;
    asm("ex2.approx.ftz.f32 %0, %1;" : "=f"(y) : "f"(x));
    return y;
}
__device__ __forceinline__ float fsigmoid(float x) {
    return __fdividef(1.0f, 1.0f + fexp2(-LOG2E * x));
}
__device__ __forceinline__ float fadef(int i) {
    float v = 1.0f;
    if (i < 4)   v = 0.6f + (0.4f/3.0f) * (float)i;
    if (i >= 60) v = 0.6f + (0.4f/3.0f) * (float)(63 - i);
    return v;
}
__device__ __forceinline__ int fbidx(int b, int c, int off) {
    return ((b*4 + c) << 12) + off;
}

// grid-wide barrier (all blocks co-resident: grid=64 <= 148 SMs)
__device__ __forceinline__ void grid_barrier() {
    __syncthreads();
    if (threadIdx.x == 0) {
        __threadfence();
        unsigned gen = *(volatile unsigned*)&g_bar_gen;
        unsigned old = atomicAdd(&g_bar_arrive, 1u);
        if (old == gridDim.x - 1) {
            g_bar_arrive = 0;
            __threadfence();
            *(volatile unsigned*)&g_bar_gen = gen + 1u;
        } else {
            while (*(volatile unsigned*)&g_bar_gen == gen) { }
        }
    }
    __syncthreads();
    __threadfence();
}

// ---------------- kernel 1: reverb loop (16 reflections, in-kernel sync) -----
__global__ void __launch_bounds__(256) reverb_kernel(
    const float* __restrict__ x,
    const float* __restrict__ rw,
    const float* __restrict__ rd,
    const float* __restrict__ fw,
    const float* __restrict__ fbias,
    const float* __restrict__ d1w, const float* __restrict__ d1b,
    const float* __restrict__ d2w, const float* __restrict__ d2b)
{
    __shared__ float s_fw[144];
    __shared__ float s_fb[4];
    __shared__ float s_d1w[8], s_d1b[2], s_d2w[8], s_d2b[4];
    __shared__ float s_rw[16], s_rd[16];
    __shared__ float s_fade[64];

    const int tid = threadIdx.x;
    if (tid < 144) s_fw[tid]  = fw[tid];
    if (tid < 4)   s_fb[tid]  = fbias[tid];
    if (tid < 8)   s_d1w[tid] = d1w[tid];
    if (tid < 2)   s_d1b[tid] = d1b[tid];
    if (tid < 8)   s_d2w[tid] = d2w[tid];
    if (tid < 4)   s_d2b[tid] = d2b[tid];
    if (tid < 16)  { s_rw[tid] = rw[tid]; s_rd[tid] = rd[tid]; }
    if (tid < 64)  s_fade[tid] = fadef(tid);
    __syncthreads();

    const int blk = blockIdx.x;
    const int b   = blk >> 4;
    const int y   = ((blk & 15) << 2) + (tid >> 6);
    const int xx  = tid & 63;
    const int off = (y << 6) + xx;

    float wetr[4], fbreg[4];
    #pragma unroll
    for (int c = 0; c < 4; c++) {
        fbreg[c] = 0.1f * x[fbidx(b, c, off)];
        g_fbA[fbidx(b, c, off)] = fbreg[c];
        wetr[c] = 0.0f;
    }
    grid_barrier();

    float decay = 1.0f;
    for (int i = 0; i < 16; i++) {
        const float dly = s_rd[i] * 3.0f;           // ROOM*12*rsf = 3
        const int ys = ((int)floorf(dly))        & 63;
        const int xs = ((int)floorf(2.0f * dly)) & 63;
        const float wgt    = fsigmoid(s_rw[i]) * decay * 1.5f;  // 1 + FB*fbscale
        const float wscale = wgt * 2.0f;                         // * 4*rsf

        // r = conv3x3(delay_line(fbA))
        float r[4] = { s_fb[0], s_fb[1], s_fb[2], s_fb[3] };
        #pragma unroll
        for (int dy = -1; dy <= 1; dy++) {
            const int yy = y + dy;
            if ((unsigned)yy >= 64u) continue;
            const float fy   = s_fade[yy];
            const int   ysrc = (yy - ys) & 63;
            #pragma unroll
            for (int dx = -1; dx <= 1; dx++) {
                const int xx2 = xx + dx;
                if ((unsigned)xx2 >= 64u) continue;
                const float ff   = fy * s_fade[xx2];
                const int   xsrc = (xx2 - xs) & 63;
                const int   soff = (ysrc << 6) + xsrc;
                const int   wtap = (dy + 1) * 3 + (dx + 1);
                #pragma unroll
                for (int ic = 0; ic < 4; ic++) {
                    const float v = __ldcg(&g_fbA[fbidx(b, ic, soff)]) * ff;
                    r[0] = fmaf(s_fw[(0*4 + ic)*9 + wtap], v, r[0]);
                    r[1] = fmaf(s_fw[(1*4 + ic)*9 + wtap], v, r[1]);
                    r[2] = fmaf(s_fw[(2*4 + ic)*9 + wtap], v, r[2]);
                    r[3] = fmaf(s_fw[(3*4 + ic)*9 + wtap], v, r[3]);
                }
            }
        }

        // damping MLP (1x1 -> silu -> 1x1 -> sigmoid)
        float u0 = s_d1b[0], u1 = s_d1b[1];
        #pragma unroll
        for (int c = 0; c < 4; c++) {
            u0 = fmaf(s_d1w[c],     r[c], u0);
            u1 = fmaf(s_d1w[4 + c], r[c], u1);
        }
        u0 = u0 * fsigmoid(u0);
        u1 = u1 * fsigmoid(u1);

        #pragma unroll
        for (int c = 0; c < 4; c++) {
            const float dmp = fsigmoid(s_d2b[c] + s_d2w[c*2]*u0 + s_d2w[c*2+1]*u1);
            const float rdc = r[c] * dmp;
            wetr[c]  = fmaf(rdc, wscale, wetr[c]);
            fbreg[c] = fmaf(rdc, 0.24f, fbreg[c]);   // FEEDBACK*1.2*rsf
            g_fbB[fbidx(b, c, off)] = fbreg[c];
        }
        grid_barrier();

        // second reflection mix (FEEDBACK>0.3, i>0)
        if (i > 0) {
            const int ys2 = ((int)floorf(dly * 0.5f)) & 63;
            const int xs2 = ((int)floorf(dly))        & 63;
            const int soff = (((y - ys2) & 63) << 6) + ((xx - xs2) & 63);
            const float ffp = s_fade[y] * s_fade[xx];
            #pragma unroll
            for (int c = 0; c < 4; c++) {
                const float prev = __ldcg(&g_fbB[fbidx(b, c, soff)]) * ffp;
                fbreg[c] = fmaf(prev, 0.08f, fbreg[c]);  // FEEDBACK*0.4*rsf
            }
        }
        #pragma unroll
        for (int c = 0; c < 4; c++)
            g_fbA[fbidx(b, c, off)] = fbreg[c];
        grid_barrier();

        decay *= 0.8f;
    }

    #pragma unroll
    for (int c = 0; c < 4; c++)
        g_wet[fbidx(b, c, off)] = wetr[c];
}

// ---------------- kernel 2: qkv projection ----------------------------------
__global__ void __launch_bounds__(256) qkv_kernel(
    const float* __restrict__ aiw, const float* __restrict__ aib)
{
    __shared__ float s_w[48], s_b[12];
    const int tid = threadIdx.x;
    if (tid < 48) s_w[tid] = aiw[tid];
    if (tid < 12) s_b[tid] = aib[tid];
    __syncthreads();

    const int p = blockIdx.x * 256 + tid;
    const int b = p >> 12;
    const int s = p & 4095;

    float in[4];
    #pragma unroll
    for (int c = 0; c < 4; c++) in[c] = g_wet[fbidx(b, c, s)];

    #pragma unroll
    for (int h = 0; h < 4; h++) {
        float q = s_b[h], k = s_b[4 + h], v = s_b[8 + h];
        #pragma unroll
        for (int c = 0; c < 4; c++) {
            q = fmaf(s_w[h*4 + c],       in[c], q);
            k = fmaf(s_w[(4 + h)*4 + c], in[c], k);
            v = fmaf(s_w[(8 + h)*4 + c], in[c], v);
        }
        const int base = ((b*4 + h) << 12) + s;
        g_q[base]  = q;
        g_kv[base] = make_float2(k, v);
    }
}

// ---------------- kernel 3: rank-1 softmax attention -------------------------
// head_dim = 1: o[q] = sum_j v_j e^{a_q k_j} / sum_j e^{a_q k_j}
__global__ void __launch_bounds__(256) attn_kernel()
{
    __shared__ float2 skv[4096];
    __shared__ float  smax[8], smin[8];

    const int tid  = threadIdx.x;
    const int bh   = blockIdx.x >> 4;
    const int base = bh << 12;

    float kmax = -1e30f, kmin = 1e30f;
    for (int j = tid; j < 4096; j += 256) {
        const float2 kv = g_kv[base + j];
        skv[j] = kv;
        kmax = fmaxf(kmax, kv.x);
        kmin = fminf(kmin, kv.x);
    }
    #pragma unroll
    for (int o = 16; o > 0; o >>= 1) {
        kmax = fmaxf(kmax, __shfl_xor_sync(0xFFFFFFFFu, kmax, o));
        kmin = fminf(kmin, __shfl_xor_sync(0xFFFFFFFFu, kmin, o));
    }
    if ((tid & 31) == 0) { smax[tid >> 5] = kmax; smin[tid >> 5] = kmin; }
    __syncthreads();
    kmax = smax[0]; kmin = smin[0];
    #pragma unroll
    for (int w = 1; w < 8; w++) {
        kmax = fmaxf(kmax, smax[w]);
        kmin = fminf(kmin, smin[w]);
    }

    const int   s   = ((blockIdx.x & 15) << 8) + tid;
    const float a2  = g_q[base + s] * LOG2E;
    const float nm2 = -fmaxf(a2 * kmax, a2 * kmin);   // -(log2-domain row max)

    float num = 0.0f, den = 0.0f;
    #pragma unroll 8
    for (int j = 0; j < 4096; j++) {
        const float2 kv = skv[j];
        const float  e  = fexp2(fmaf(a2, kv.x, nm2));
        num = fmaf(e, kv.y, num);
        den += e;
    }
    g_o[base + s] = __fdividef(num, den);
}

// ---------------- kernel 4: out-projection fused with 3x3 box blur -----------
__global__ void __launch_bounds__(256) blurproj_kernel(
    const float* __restrict__ aow, const float* __restrict__ aob)
{
    __shared__ float s_w[16], s_b[4];
    const int tid = threadIdx.x;
    if (tid < 16) s_w[tid] = aow[tid];
    if (tid < 4)  s_b[tid] = aob[tid];
    __syncthreads();

    const int p  = blockIdx.x * 256 + tid;
    const int b  = p >> 12;
    const int s  = p & 4095;
    const int y  = s >> 6;
    const int xx = s & 63;

    float acc[4] = {0.f, 0.f, 0.f, 0.f};
    #pragma unroll
    for (int dy = -1; dy <= 1; dy++) {
        const int yy = y + dy;
        if ((unsigned)yy >= 64u) continue;
        #pragma unroll
        for (int dx = -1; dx <= 1; dx++) {
            const int xx2 = xx + dx;
            if ((unsigned)xx2 >= 64u) continue;
            const int s2 = (yy << 6) + xx2;
            float o0 = g_o[((b*4 + 0) << 12) + s2];
            float o1 = g_o[((b*4 + 1) << 12) + s2];
            float o2 = g_o[((b*4 + 2) << 12) + s2];
            float o3 = g_o[((b*4 + 3) << 12) + s2];
            #pragma unroll
            for (int c = 0; c < 4; c++) {
                float w2 = s_b[c];
                w2 = fmaf(s_w[c*4 + 0], o0, w2);
                w2 = fmaf(s_w[c*4 + 1], o1, w2);
                w2 = fmaf(s_w[c*4 + 2], o2, w2);
                w2 = fmaf(s_w[c*4 + 3], o3, w2);
                acc[c] += w2;
            }
        }
    }
    #pragma unroll
    for (int c = 0; c < 4; c++)
        g_wet3[fbidx(b, c, s)] = acc[c] * (1.0f/9.0f);
}

// ---------------- kernel 5: edge enhance + spatial conv + 1x1 out + mix ------
__global__ void __launch_bounds__(256) final_kernel(
    const float* __restrict__ x,
    const float* __restrict__ spw, const float* __restrict__ spb,
    const float* __restrict__ ow,  const float* __restrict__ ob,
    float* __restrict__ out)
{
    __shared__ float s_spw[288], s_spb[8], s_ow[48], s_ob[4];
    const int tid = threadIdx.x;
    for (int i = tid; i < 288; i += 256) s_spw[i] = spw[i];
    if (tid < 8)  s_spb[tid] = spb[tid];
    if (tid < 48) s_ow[tid]  = ow[tid];
    if (tid < 4)  s_ob[tid]  = ob[tid];
    __syncthreads();

    const int p  = blockIdx.x * 256 + tid;
    const int b  = p >> 12;
    const int s  = p & 4095;
    const int y  = s >> 6;
    const int xx = s & 63;

    // edge enhancement on blurred wet
    float ctr[4], nsum[4] = {0.f, 0.f, 0.f, 0.f};
    #pragma unroll
    for (int c = 0; c < 4; c++) ctr[c] = g_wet3[fbidx(b, c, s)];
    #pragma unroll
    for (int dy = -1; dy <= 1; dy++) {
        const int yy = y + dy;
        if ((unsigned)yy >= 64u) continue;
        #pragma unroll
        for (int dx = -1; dx <= 1; dx++) {
            if (dy == 0 && dx == 0) continue;
            const int xx2 = xx + dx;
            if ((unsigned)xx2 >= 64u) continue;
            const int s2 = (yy << 6) + xx2;
            #pragma unroll
            for (int c = 0; c < 4; c++) nsum[c] += g_wet3[fbidx(b, c, s2)];
        }
    }
    float wet4[4];
    #pragma unroll
    for (int c = 0; c < 4; c++) {
        const float edge = 8.0f * ctr[c] - nsum[c];
        wet4[c] = fmaf(edge, 0.04f, ctr[c]);   // FEEDBACK*0.2*rsf
    }

    // spatial features = conv3x3(x) -> 8 channels
    float sf[8];
    #pragma unroll
    for (int o = 0; o < 8; o++) sf[o] = s_spb[o];
    #pragma unroll
    for (int dy = -1; dy <= 1; dy++) {
        const int yy = y + dy;
        if ((unsigned)yy >= 64u) continue;
        #pragma unroll
        for (int dx = -1; dx <= 1; dx++) {
            const int xx2 = xx + dx;
            if ((unsigned)xx2 >= 64u) continue;
            const int s2   = (yy << 6) + xx2;
            const int wtap = (dy + 1) * 3 + (dx + 1);
            #pragma unroll
            for (int ic = 0; ic < 4; ic++) {
                const float v = x[fbidx(b, ic, s2)];
                #pragma unroll
                for (int o = 0; o < 8; o++)
                    sf[o] = fmaf(s_spw[(o*4 + ic)*9 + wtap], v, sf[o]);
            }
        }
    }

    // 1x1 out conv over concat([sf(8), wet4(4)]) + dry/wet mix
    #pragma unroll
    for (int c = 0; c < 4; c++) {
        float pr = s_ob[c];
        #pragma unroll
        for (int j = 0; j < 8; j++) pr = fmaf(s_ow[c*12 + j],     sf[j],   pr);
        #pragma unroll
        for (int j = 0; j < 4; j++) pr = fmaf(s_ow[c*12 + 8 + j], wet4[j], pr);
        const int idx = fbidx(b, c, s);
        out[idx] = fmaf(x[idx], 0.7f, 0.3f * pr);
    }
}

// ---------------- launcher ---------------------------------------------------
extern "C" void kernel_launch(void* const* d_in, const int* in_sizes, int n_in,
                              void* d_out, int out_size)
{
    const float* x   = (const float*)d_in[0];
    const float* rw  = (const float*)d_in[1];
    const float* rd  = (const float*)d_in[2];
    // d_in[3] = diffusion_strength (unused by reference)
    const float* spw = (const float*)d_in[4];
    const float* spb = (const float*)d_in[5];
    const float* fw  = (const float*)d_in[6];
    const float* fb  = (const float*)d_in[7];
    const float* d1w = (const float*)d_in[8];
    const float* d1b = (const float*)d_in[9];
    const float* d2w = (const float*)d_in[10];
    const float* d2b = (const float*)d_in[11];
    const float* aiw = (const float*)d_in[12];
    const float* aib = (const float*)d_in[13];
    const float* aow = (const float*)d_in[14];
    const float* aob = (const float*)d_in[15];
    const float* ow  = (const float*)d_in[16];
    const float* ob  = (const float*)d_in[17];
    float* out = (float*)d_out;

    reverb_kernel  <<< 64, 256>>>(x, rw, rd, fw, fb, d1w, d1b, d2w, d2b);
    qkv_kernel     <<< 64, 256>>>(aiw, aib);
    attn_kernel    <<<256, 256>>>();
    blurproj_kernel<<< 64, 256>>>(aow, aob);
    final_kernel   <<< 64, 256>>>(x, spw, spb, ow, ob, out);
}

// round 4
// speedup vs baseline: 1.0435x; 1.0435x over previous
#include <cuda_runtime.h>

// LatentReverb: B=4, C=4, H=W=64, NREF=16
// DECAY=0.8, WET_MIX=0.3, FEEDBACK=0.4, ROOM=0.5, HEADS=4 (head_dim=1)

#define BB 4
#define LOG2E 1.4426950408889634f

// ---------------- scratch (static device globals; no allocation) -------------
__device__ float4 g_fbA4 [BB*4096];
__device__ float4 g_fbB4 [BB*4096];
__device__ float4 g_q4   [BB*4096];   // per-pixel q for 4 heads
__device__ float2 g_kv   [16*4096];   // per (b,h): k,v
__device__ float  g_table[16*256];    // per (b,h): softmax-output table over a-grid
__device__ float2 g_meta [16];        // (amin, h_step) per (b,h)
__device__ float4 g_o4   [BB*4096];   // attention output, 4 heads per pixel
__device__ float4 g_w34  [BB*4096];   // blurred+projected wet

// ---------------- helpers ----------------------------------------------------
__device__ __forceinline__ float fexp2(float x) {
    float y;
    asm("ex2.approx.ftz.f32 %0, %1;" : "=f"(y) : "f"(x));
    return y;
}
__device__ __forceinline__ float fsigmoid(float x) {
    return __fdividef(1.0f, 1.0f + fexp2(-LOG2E * x));
}
__device__ __forceinline__ float fadef(int i) {
    float v = 1.0f;
    if (i < 4)   v = 0.6f + (0.4f/3.0f) * (float)i;
    if (i >= 60) v = 0.6f + (0.4f/3.0f) * (float)(63 - i);
    return v;
}
__device__ __forceinline__ void cluster_sync() {
    asm volatile("barrier.cluster.arrive.aligned;" ::: "memory");
    asm volatile("barrier.cluster.wait.aligned;"   ::: "memory");
}

// ---------------- kernel 1: reverb loop + fused qkv ---------------------------
// grid (8,4): cluster of 8 CTAs (512 thr each) per batch image. 1 thread/pixel.
__global__ void __cluster_dims__(8,1,1) __launch_bounds__(512, 1) reverb_kernel(
    const float* __restrict__ x,
    const float* __restrict__ rw,
    const float* __restrict__ rd,
    const float* __restrict__ fw,
    const float* __restrict__ fbias,
    const float* __restrict__ d1w, const float* __restrict__ d1b,
    const float* __restrict__ d2w, const float* __restrict__ d2b,
    const float* __restrict__ aiw, const float* __restrict__ aib)
{
    __shared__ float s_fw2[144];               // [tap][ic][oc]
    __shared__ float s_fb[4];
    __shared__ float s_d1w[8], s_d1b[2], s_d2w[8], s_d2b[4];
    __shared__ float s_rw[16], s_rd[16];
    __shared__ float s_fade[64];
    __shared__ float s_aiw[48], s_aib[12];

    const int tid = threadIdx.x;
    if (tid < 144) {
        const int tap = tid >> 4, r = tid & 15;
        const int ic = r >> 2, oc = r & 3;
        s_fw2[tid] = fw[(oc*4 + ic)*9 + tap];
    }
    if (tid < 4)   s_fb[tid]  = fbias[tid];
    if (tid < 8)   s_d1w[tid] = d1w[tid];
    if (tid < 2)   s_d1b[tid] = d1b[tid];
    if (tid < 8)   s_d2w[tid] = d2w[tid];
    if (tid < 4)   s_d2b[tid] = d2b[tid];
    if (tid < 16)  { s_rw[tid] = rw[tid]; s_rd[tid] = rd[tid]; }
    if (tid < 64)  s_fade[tid] = fadef(tid);
    if (tid < 48)  s_aiw[tid] = aiw[tid];
    if (tid < 12)  s_aib[tid] = aib[tid];
    __syncthreads();

    const int b     = blockIdx.y;
    const int y     = (blockIdx.x << 3) + (tid >> 6);
    const int xx    = tid & 63;
    const int off   = (y << 6) + xx;
    const int pbase = b << 12;

    float fb0 = 0.1f * x[((b*4 + 0) << 12) + off];
    float fb1 = 0.1f * x[((b*4 + 1) << 12) + off];
    float fb2 = 0.1f * x[((b*4 + 2) << 12) + off];
    float fb3 = 0.1f * x[((b*4 + 3) << 12) + off];
    g_fbA4[pbase + off] = make_float4(fb0, fb1, fb2, fb3);
    float w0 = 0.f, w1 = 0.f, w2 = 0.f, w3 = 0.f;
    cluster_sync();

    float decay = 1.0f;
    for (int i = 0; i < 16; i++) {
        const float dly = s_rd[i] * 3.0f;            // ROOM*12*rsf = 3 (exact int)
        const int ys = ((int)dly)          & 63;
        const int xs = ((int)(2.0f * dly)) & 63;
        const float wgt    = fsigmoid(s_rw[i]) * decay * 1.5f;
        const float wscale = wgt * 2.0f;

        // r = conv3x3(fade * roll(fbA))
        float r0 = s_fb[0], r1 = s_fb[1], r2 = s_fb[2], r3 = s_fb[3];
        #pragma unroll
        for (int dy = -1; dy <= 1; dy++) {
            const int yy = y + dy;
            if ((unsigned)yy >= 64u) continue;
            const float fy   = s_fade[yy];
            const int   ysrc = (yy - ys) & 63;
            #pragma unroll
            for (int dx = -1; dx <= 1; dx++) {
                const int xx2 = xx + dx;
                if ((unsigned)xx2 >= 64u) continue;
                const float ff   = fy * s_fade[xx2];
                const int   soff = (ysrc << 6) + ((xx2 - xs) & 63);
                const float4 v  = __ldcg(&g_fbA4[pbase + soff]);
                const float vx = v.x*ff, vy = v.y*ff, vz = v.z*ff, vw = v.w*ff;
                const float* w = &s_fw2[((dy + 1)*3 + (dx + 1)) << 4];
                r0 = fmaf(w[0],  vx, r0); r1 = fmaf(w[1],  vx, r1);
                r2 = fmaf(w[2],  vx, r2); r3 = fmaf(w[3],  vx, r3);
                r0 = fmaf(w[4],  vy, r0); r1 = fmaf(w[5],  vy, r1);
                r2 = fmaf(w[6],  vy, r2); r3 = fmaf(w[7],  vy, r3);
                r0 = fmaf(w[8],  vz, r0); r1 = fmaf(w[9],  vz, r1);
                r2 = fmaf(w[10], vz, r2); r3 = fmaf(w[11], vz, r3);
                r0 = fmaf(w[12], vw, r0); r1 = fmaf(w[13], vw, r1);
                r2 = fmaf(w[14], vw, r2); r3 = fmaf(w[15], vw, r3);
            }
        }

        // damping MLP (1x1 -> silu -> 1x1 -> sigmoid)
        float u0 = s_d1b[0], u1 = s_d1b[1];
        u0 = fmaf(s_d1w[0], r0, u0); u1 = fmaf(s_d1w[4], r0, u1);
        u0 = fmaf(s_d1w[1], r1, u0); u1 = fmaf(s_d1w[5], r1, u1);
        u0 = fmaf(s_d1w[2], r2, u0); u1 = fmaf(s_d1w[6], r2, u1);
        u0 = fmaf(s_d1w[3], r3, u0); u1 = fmaf(s_d1w[7], r3, u1);
        u0 = u0 * fsigmoid(u0);
        u1 = u1 * fsigmoid(u1);

        const float rd0 = r0 * fsigmoid(s_d2b[0] + s_d2w[0]*u0 + s_d2w[1]*u1);
        const float rd1 = r1 * fsigmoid(s_d2b[1] + s_d2w[2]*u0 + s_d2w[3]*u1);
        const float rd2 = r2 * fsigmoid(s_d2b[2] + s_d2w[4]*u0 + s_d2w[5]*u1);
        const float rd3 = r3 * fsigmoid(s_d2b[3] + s_d2w[6]*u0 + s_d2w[7]*u1);

        w0 = fmaf(rd0, wscale, w0); w1 = fmaf(rd1, wscale, w1);
        w2 = fmaf(rd2, wscale, w2); w3 = fmaf(rd3, wscale, w3);
        fb0 = fmaf(rd0, 0.24f, fb0); fb1 = fmaf(rd1, 0.24f, fb1);
        fb2 = fmaf(rd2, 0.24f, fb2); fb3 = fmaf(rd3, 0.24f, fb3);
        g_fbB4[pbase + off] = make_float4(fb0, fb1, fb2, fb3);
        cluster_sync();

        // second reflection mix (FEEDBACK>0.3, i>0)
        if (i > 0) {
            const int ys2 = ((int)(dly * 0.5f)) & 63;
            const int xs2 = ((int)dly)          & 63;
            const int soff = (((y - ys2) & 63) << 6) + ((xx - xs2) & 63);
            const float ffp = s_fade[y] * s_fade[xx];
            const float4 pv = __ldcg(&g_fbB4[pbase + soff]);
            fb0 = fmaf(pv.x * ffp, 0.08f, fb0);
            fb1 = fmaf(pv.y * ffp, 0.08f, fb1);
            fb2 = fmaf(pv.z * ffp, 0.08f, fb2);
            fb3 = fmaf(pv.w * ffp, 0.08f, fb3);
        }
        g_fbA4[pbase + off] = make_float4(fb0, fb1, fb2, fb3);
        cluster_sync();

        decay *= 0.8f;
    }

    // fused qkv projection from wet registers
    float qh[4];
    #pragma unroll
    for (int h = 0; h < 4; h++) {
        float q = s_aib[h], k = s_aib[4 + h], v = s_aib[8 + h];
        q = fmaf(s_aiw[h*4+0],     w0, q); q = fmaf(s_aiw[h*4+1],     w1, q);
        q = fmaf(s_aiw[h*4+2],     w2, q); q = fmaf(s_aiw[h*4+3],     w3, q);
        k = fmaf(s_aiw[(4+h)*4+0], w0, k); k = fmaf(s_aiw[(4+h)*4+1], w1, k);
        k = fmaf(s_aiw[(4+h)*4+2], w2, k); k = fmaf(s_aiw[(4+h)*4+3], w3, k);
        v = fmaf(s_aiw[(8+h)*4+0], w0, v); v = fmaf(s_aiw[(8+h)*4+1], w1, v);
        v = fmaf(s_aiw[(8+h)*4+2], w2, v); v = fmaf(s_aiw[(8+h)*4+3], w3, v);
        qh[h] = q;
        g_kv[((b*4 + h) << 12) + off] = make_float2(k, v);
    }
    g_q4[pbase + off] = make_float4(qh[0], qh[1], qh[2], qh[3]);
}

// ---------------- kernel 2: softmax table eval -------------------------------
// head_dim=1 => o[q] = F(a_q), F smooth. Tabulate F at 256 points per (b,h).
// 128 blocks: 8 per (b,h); all 8 compute identical (exact) min/max.
__global__ void __launch_bounds__(256) tableeval_kernel()
{
    __shared__ float2 skv[4096];
    __shared__ float  red[4][8];

    const int tid   = threadIdx.x;
    const int bh    = blockIdx.x >> 3;
    const int chunk = blockIdx.x & 7;
    const int base  = bh << 12;
    const int b     = bh >> 2, h = bh & 3;

    float kmin = 1e30f, kmax = -1e30f, amin = 1e30f, amax = -1e30f;
    const float* qptr = (const float*)g_q4 + ((b << 12) << 2) + h;
    for (int j = tid; j < 4096; j += 256) {
        const float2 kv = g_kv[base + j];
        skv[j] = kv;
        kmax = fmaxf(kmax, kv.x); kmin = fminf(kmin, kv.x);
        const float a = qptr[j << 2];
        amax = fmaxf(amax, a); amin = fminf(amin, a);
    }
    #pragma unroll
    for (int o = 16; o > 0; o >>= 1) {
        kmin = fminf(kmin, __shfl_xor_sync(0xFFFFFFFFu, kmin, o));
        kmax = fmaxf(kmax, __shfl_xor_sync(0xFFFFFFFFu, kmax, o));
        amin = fminf(amin, __shfl_xor_sync(0xFFFFFFFFu, amin, o));
        amax = fmaxf(amax, __shfl_xor_sync(0xFFFFFFFFu, amax, o));
    }
    if ((tid & 31) == 0) {
        red[0][tid >> 5] = kmin; red[1][tid >> 5] = kmax;
        red[2][tid >> 5] = amin; red[3][tid >> 5] = amax;
    }
    __syncthreads();
    kmin = red[0][0]; kmax = red[1][0]; amin = red[2][0]; amax = red[3][0];
    #pragma unroll
    for (int w = 1; w < 8; w++) {
        kmin = fminf(kmin, red[0][w]); kmax = fmaxf(kmax, red[1][w]);
        amin = fminf(amin, red[2][w]); amax = fmaxf(amax, red[3][w]);
    }
    const float hs = fmaxf((amax - amin) * (1.0f/252.0f), 1e-30f);
    if (chunk == 0 && tid == 0) g_meta[bh] = make_float2(amin, hs);

    // grid node: a_g = amin + (g-1)*hs, g in [0,255]; 8 lanes split the j-sum
    const int   g     = (chunk << 5) + (tid >> 3);
    const int   slice = tid & 7;
    const float a     = amin + (float)(g - 1) * hs;
    const float a2    = a * LOG2E;
    const float m2    = fmaxf(a2 * kmin, a2 * kmax);

    float num = 0.f, den = 0.f;
    const float2* p = &skv[slice << 9];
    #pragma unroll 8
    for (int j = 0; j < 512; j++) {
        const float2 kv = p[j];
        const float  e  = fexp2(fmaf(a2, kv.x, -m2));
        num = fmaf(e, kv.y, num);
        den += e;
    }
    #pragma unroll
    for (int o = 4; o > 0; o >>= 1) {
        num += __shfl_xor_sync(0xFFFFFFFFu, num, o);
        den += __shfl_xor_sync(0xFFFFFFFFu, den, o);
    }
    if (slice == 0) g_table[(bh << 8) + g] = __fdividef(num, den);
}

// ---------------- kernel 3: per-query cubic Lagrange interpolation ------------
__global__ void __launch_bounds__(256) interp_kernel()
{
    __shared__ float  s_tab[4096];
    __shared__ float2 s_meta[16];
    const int tid = threadIdx.x;
    for (int i = tid; i < 4096; i += 256) s_tab[i] = g_table[i];
    if (tid < 16) s_meta[tid] = g_meta[tid];
    __syncthreads();

    const int p = blockIdx.x * 256 + tid;
    const int b = p >> 12;
    const float4 q = g_q4[p];
    const float qa[4] = { q.x, q.y, q.z, q.w };
    float oh[4];
    #pragma unroll
    for (int h = 0; h < 4; h++) {
        const float2 m  = s_meta[b*4 + h];
        float sr = (qa[h] - m.x) * __fdividef(1.0f, m.y);
        sr = fminf(fmaxf(sr, 0.0f), 252.0f);
        const float fi = floorf(sr);
        const int   i0 = (int)fi;
        const float f  = sr - fi;
        const float* t = &s_tab[((b*4 + h) << 8) + i0];
        // 4-pt Lagrange on nodes -1,0,1,2 evaluated at f in [0,1]
        const float fm1 = f + 1.0f, f1 = f - 1.0f, f2 = f - 2.0f;
        const float c0 = -f  * f1 * f2 * (1.0f/6.0f);
        const float c1 =  fm1 * f1 * f2 * 0.5f;
        const float c2 = -fm1 * f  * f2 * 0.5f;
        const float c3 =  fm1 * f  * f1 * (1.0f/6.0f);
        oh[h] = c0*t[0] + c1*t[1] + c2*t[2] + c3*t[3];
    }
    g_o4[p] = make_float4(oh[0], oh[1], oh[2], oh[3]);
}

// ---------------- kernel 4: box blur (3x3) fused with out-projection ----------
__global__ void __launch_bounds__(256) blurproj_kernel(
    const float* __restrict__ aow, const float* __restrict__ aob)
{
    __shared__ float s_w[16], s_b[4];
    const int tid = threadIdx.x;
    if (tid < 16) s_w[tid] = aow[tid];
    if (tid < 4)  s_b[tid] = aob[tid];
    __syncthreads();

    const int p  = blockIdx.x * 256 + tid;
    const int b  = p >> 12;
    const int s  = p & 4095;
    const int y  = s >> 6;
    const int xx = s & 63;

    float sx = 0.f, sy = 0.f, sz = 0.f, sw = 0.f;
    float cnt = 0.f;
    #pragma unroll
    for (int dy = -1; dy <= 1; dy++) {
        const int yy = y + dy;
        if ((unsigned)yy >= 64u) continue;
        #pragma unroll
        for (int dx = -1; dx <= 1; dx++) {
            const int xx2 = xx + dx;
            if ((unsigned)xx2 >= 64u) continue;
            const float4 o = g_o4[(b << 12) + (yy << 6) + xx2];
            sx += o.x; sy += o.y; sz += o.z; sw += o.w;
            cnt += 1.0f;
        }
    }
    float outc[4];
    #pragma unroll
    for (int c = 0; c < 4; c++) {
        float pr = cnt * s_b[c];
        pr = fmaf(s_w[c*4+0], sx, pr); pr = fmaf(s_w[c*4+1], sy, pr);
        pr = fmaf(s_w[c*4+2], sz, pr); pr = fmaf(s_w[c*4+3], sw, pr);
        outc[c] = pr * (1.0f/9.0f);
    }
    g_w34[p] = make_float4(outc[0], outc[1], outc[2], outc[3]);
}

// ---------------- kernel 5: edge enhance + spatial conv + 1x1 out + mix -------
__global__ void __launch_bounds__(256) final_kernel(
    const float* __restrict__ x,
    const float* __restrict__ spw, const float* __restrict__ spb,
    const float* __restrict__ ow,  const float* __restrict__ ob,
    float* __restrict__ out)
{
    __shared__ float s_spw[288], s_spb[8], s_ow[48], s_ob[4];
    const int tid = threadIdx.x;
    for (int i = tid; i < 288; i += 256) s_spw[i] = spw[i];
    if (tid < 8)  s_spb[tid] = spb[tid];
    if (tid < 48) s_ow[tid]  = ow[tid];
    if (tid < 4)  s_ob[tid]  = ob[tid];
    __syncthreads();

    const int p  = blockIdx.x * 256 + tid;
    const int b  = p >> 12;
    const int s  = p & 4095;
    const int y  = s >> 6;
    const int xx = s & 63;

    // edge enhancement on blurred wet
    const float4 ctr = g_w34[p];
    float n0 = 0.f, n1 = 0.f, n2 = 0.f, n3 = 0.f;
    #pragma unroll
    for (int dy = -1; dy <= 1; dy++) {
        const int yy = y + dy;
        if ((unsigned)yy >= 64u) continue;
        #pragma unroll
        for (int dx = -1; dx <= 1; dx++) {
            if (dy == 0 && dx == 0) continue;
            const int xx2 = xx + dx;
            if ((unsigned)xx2 >= 64u) continue;
            const float4 v = g_w34[(b << 12) + (yy << 6) + xx2];
            n0 += v.x; n1 += v.y; n2 += v.z; n3 += v.w;
        }
    }
    float wet4[4];
    wet4[0] = fmaf(8.0f*ctr.x - n0, 0.04f, ctr.x);
    wet4[1] = fmaf(8.0f*ctr.y - n1, 0.04f, ctr.y);
    wet4[2] = fmaf(8.0f*ctr.z - n2, 0.04f, ctr.z);
    wet4[3] = fmaf(8.0f*ctr.w - n3, 0.04f, ctr.w);

    // spatial features = conv3x3(x) -> 8 channels
    float sf[8];
    #pragma unroll
    for (int o = 0; o < 8; o++) sf[o] = s_spb[o];
    #pragma unroll
    for (int dy = -1; dy <= 1; dy++) {
        const int yy = y + dy;
        if ((unsigned)yy >= 64u) continue;
        #pragma unroll
        for (int dx = -1; dx <= 1; dx++) {
            const int xx2 = xx + dx;
            if ((unsigned)xx2 >= 64u) continue;
            const int s2   = (yy << 6) + xx2;
            const int wtap = (dy + 1)*3 + (dx + 1);
            #pragma unroll
            for (int ic = 0; ic < 4; ic++) {
                const float v = x[((b*4 + ic) << 12) + s2];
                #pragma unroll
                for (int o = 0; o < 8; o++)
                    sf[o] = fmaf(s_spw[(o*4 + ic)*9 + wtap], v, sf[o]);
            }
        }
    }

    // 1x1 out conv over concat([sf(8), wet4(4)]) + dry/wet mix
    #pragma unroll
    for (int c = 0; c < 4; c++) {
        float pr = s_ob[c];
        #pragma unroll
        for (int j = 0; j < 8; j++) pr = fmaf(s_ow[c*12 + j],     sf[j],   pr);
        #pragma unroll
        for (int j = 0; j < 4; j++) pr = fmaf(s_ow[c*12 + 8 + j], wet4[j], pr);
        const int idx = ((b*4 + c) << 12) + s;
        out[idx] = fmaf(x[idx], 0.7f, 0.3f * pr);
    }
}

// ---------------- launcher ---------------------------------------------------
extern "C" void kernel_launch(void* const* d_in, const int* in_sizes, int n_in,
                              void* d_out, int out_size)
{
    const float* x   = (const float*)d_in[0];
    const float* rw  = (const float*)d_in[1];
    const float* rd  = (const float*)d_in[2];
    // d_in[3] = diffusion_strength (unused by reference)
    const float* spw = (const float*)d_in[4];
    const float* spb = (const float*)d_in[5];
    const float* fw  = (const float*)d_in[6];
    const float* fb  = (const float*)d_in[7];
    const float* d1w = (const float*)d_in[8];
    const float* d1b = (const float*)d_in[9];
    const float* d2w = (const float*)d_in[10];
    const float* d2b = (const float*)d_in[11];
    const float* aiw = (const float*)d_in[12];
    const float* aib = (const float*)d_in[13];
    const float* aow = (const float*)d_in[14];
    const float* aob = (const float*)d_in[15];
    const float* ow  = (const float*)d_in[16];
    const float* ob  = (const float*)d_in[17];
    float* out = (float*)d_out;

    reverb_kernel   <<<dim3(8, 4), 512>>>(x, rw, rd, fw, fb, d1w, d1b, d2w, d2b, aiw, aib);
    tableeval_kernel<<<128, 256>>>();
    interp_kernel   <<< 64, 256>>>();
    blurproj_kernel <<< 64, 256>>>(aow, aob);
    final_kernel    <<< 64, 256>>>(x, spw, spb, ow, ob, out);
}

// round 5
// speedup vs baseline: 2.1563x; 2.0664x over previous
#include <cuda_runtime.h>

// LatentReverb fused single-kernel: B=4, C=4, H=W=64, NREF=16
// DECAY=0.8, WET_MIX=0.3, FEEDBACK=0.4, ROOM=0.5, HEADS=4 (head_dim=1)

#define LOG2E 1.4426950408889634f
#define TBL_N 64          // table nodes per head
#define TBL_SPAN 60.0f    // usable intervals (sr clamped to [0, 60])

// ---------------- scratch (static device globals; no allocation) -------------
__device__ float4 g_fb[2][4*4096];   // ping-pong feedback state (channel-last)
__device__ float4 g_x4  [4*4096];    // x transposed to channel-last
__device__ float2 g_kv  [16*4096];   // per (b,h): (k, v)
__device__ float  g_red [4][8][16];  // per (b, cta): 16 partial min/max values
__device__ float  g_tab [16*TBL_N]; // per (b,h): softmax-output table
__device__ float4 g_o4  [4*4096];    // attention output (4 heads / pixel)
__device__ float4 g_w34 [4*4096];    // blurred + projected wet

// ---------------- helpers ----------------------------------------------------
__device__ __forceinline__ float fexp2(float x) {
    float y;
    asm("ex2.approx.ftz.f32 %0, %1;" : "=f"(y) : "f"(x));
    return y;
}
__device__ __forceinline__ float fsig(float x) {
    return __fdividef(1.0f, 1.0f + fexp2(-LOG2E * x));
}
__device__ __forceinline__ float fadef(int i) {
    float v = 1.0f;
    if (i < 4)   v = 0.6f + (0.4f/3.0f) * (float)i;
    if (i >= 60) v = 0.6f + (0.4f/3.0f) * (float)(63 - i);
    return v;
}
__device__ __forceinline__ void csync() {
    asm volatile("barrier.cluster.arrive.aligned;" ::: "memory");
    asm volatile("barrier.cluster.wait.aligned;"   ::: "memory");
}
__device__ __forceinline__ void stg4(float4* p, float4 v) {
    __stcg(p, v);
}

// ---------------- the one kernel ---------------------------------------------
// grid (8,4): cluster of 8 CTAs per batch image; 512 threads; 1 thread/pixel.
__global__ void __cluster_dims__(8,1,1) __launch_bounds__(512, 1) fused_kernel(
    const float* __restrict__ x,
    const float* __restrict__ rw,  const float* __restrict__ rd,
    const float* __restrict__ fw,  const float* __restrict__ fbias,
    const float* __restrict__ d1w, const float* __restrict__ d1b,
    const float* __restrict__ d2w, const float* __restrict__ d2b,
    const float* __restrict__ aiw, const float* __restrict__ aib,
    const float* __restrict__ aow, const float* __restrict__ aob,
    const float* __restrict__ spw, const float* __restrict__ spb,
    const float* __restrict__ ow,  const float* __restrict__ ob,
    float* __restrict__ out)
{
    // union scratch: sA (2560 floats) / kv (8192 floats) / tab (256 floats)
    __shared__ __align__(16) float s_buf[8192];
    __shared__ float s_fw2[144];               // conv weights [tap][ic][oc]
    __shared__ float s_cb[4];
    __shared__ float s_d1w[8], s_d1b[2], s_d2w[8], s_d2b[4];
    __shared__ float s_rw[16], s_rd[16], s_fade[64];
    __shared__ float s_aiw[48], s_aib[12], s_aow[16], s_aob[4];
    __shared__ float s_spw[288], s_spb[8], s_ow[48], s_ob[4];
    __shared__ float s_red[16][16];            // per-warp minmax partials
    __shared__ float s_meta[16];               // cluster-reduced minmax

    const int tid  = threadIdx.x;
    const int rank = blockIdx.x;               // cluster CTA rank (stripe)
    const int b    = blockIdx.y;

    // ---- weight staging --------------------------------------------------
    if (tid < 144) {
        const int tap = tid >> 4, r = tid & 15;
        s_fw2[tid] = fw[((r & 3)*4 + (r >> 2))*9 + tap];   // [tap][ic][oc]
    }
    if (tid < 4)   s_cb[tid]  = fbias[tid];
    if (tid < 8)   s_d1w[tid] = d1w[tid];
    if (tid < 2)   s_d1b[tid] = d1b[tid];
    if (tid < 8)   s_d2w[tid] = d2w[tid];
    if (tid < 4)   s_d2b[tid] = d2b[tid];
    if (tid < 16)  { s_rw[tid] = rw[tid]; s_rd[tid] = rd[tid]; }
    if (tid < 64)  s_fade[tid] = fadef(tid);
    if (tid < 48)  s_aiw[tid] = aiw[tid];
    if (tid < 12)  s_aib[tid] = aib[tid];
    if (tid < 16)  s_aow[tid] = aow[tid];
    if (tid < 4)   s_aob[tid] = aob[tid];
    {
        int i = tid; if (i < 288) s_spw[i] = spw[i];
        i = tid - 288; if (i >= 0 && i < 8)  s_spb[i] = spb[i];
        i = tid - 296; if (i >= 0 && i < 48) s_ow[i]  = ow[i];
        i = tid - 344; if (i >= 0 && i < 4)  s_ob[i]  = ob[i];
    }
    __syncthreads();

    const int y0    = rank << 3;
    const int y     = y0 + (tid >> 6);
    const int xx    = tid & 63;
    const int off   = (y << 6) + xx;
    const int pbase = b << 12;

    // ---- phase A init: fb = 0.1*x; transpose x to channel-last -----------
    const float x0 = x[((b*4 + 0) << 12) + off];
    const float x1 = x[((b*4 + 1) << 12) + off];
    const float x2 = x[((b*4 + 2) << 12) + off];
    const float x3 = x[((b*4 + 3) << 12) + off];
    stg4(&g_x4[pbase + off], make_float4(x0, x1, x2, x3));
    float fb0 = 0.1f*x0, fb1 = 0.1f*x1, fb2 = 0.1f*x2, fb3 = 0.1f*x3;
    stg4(&g_fb[0][pbase + off], make_float4(fb0, fb1, fb2, fb3));
    float w0 = 0.f, w1 = 0.f, w2 = 0.f, w3 = 0.f;
    csync();

    // ---- phase A: 16 reflections, ONE cluster sync per iteration ---------
    float4* sA = (float4*)s_buf;               // [10 rows][64 cols]
    float decay = 1.0f;
    int ys2p = 0, xs2p = 0;                    // prev-iteration second-roll shift
    for (int j = 0; j < 16; j++) {
        const float dly = s_rd[j] * 3.0f;      // ROOM*12*rsf = 3 (exact int)
        const int ys = ((int)dly)          & 63;
        const int xs = ((int)(2.0f * dly)) & 63;
        const float wscale = fsig(s_rw[j]) * decay * 3.0f;  // 1.5 * 2.0

        // stage conv input rows: fbA(p) = fbB(p) + 0.08*fade(p)*fbB(p - s2prev)
        const float4* Bp = g_fb[j & 1] + pbase;
        #pragma unroll 2
        for (int e = tid; e < 640; e += 512) {
            const int r = e >> 6, px = e & 63;
            const int srow = (y0 - 1 + r - ys) & 63;
            float4 v = __ldcg((const float4*)&Bp[(srow << 6) + px]);
            if (j >= 2) {
                const float t  = 0.08f * s_fade[srow] * s_fade[px];
                const float4 v2 = __ldcg((const float4*)
                    &Bp[(((srow - ys2p) & 63) << 6) + ((px - xs2p) & 63)]);
                v.x = fmaf(t, v2.x, v.x); v.y = fmaf(t, v2.y, v.y);
                v.z = fmaf(t, v2.z, v.z); v.w = fmaf(t, v2.w, v.w);
            }
            sA[e] = v;
        }
        // own fbA (running feedback incl. second roll)
        float fA0 = fb0, fA1 = fb1, fA2 = fb2, fA3 = fb3;
        if (j >= 2) {
            const float t  = 0.08f * s_fade[y] * s_fade[xx];
            const float4 v2 = __ldcg((const float4*)
                &Bp[(((y - ys2p) & 63) << 6) + ((xx - xs2p) & 63)]);
            fA0 = fmaf(t, v2.x, fA0); fA1 = fmaf(t, v2.y, fA1);
            fA2 = fmaf(t, v2.z, fA2); fA3 = fmaf(t, v2.w, fA3);
        }
        __syncthreads();

        // conv3x3 over faded, rolled fbA (from SMEM)
        float r0 = s_cb[0], r1 = s_cb[1], r2 = s_cb[2], r3 = s_cb[3];
        #pragma unroll
        for (int dy = -1; dy <= 1; dy++) {
            const int yy = y + dy;
            if ((unsigned)yy >= 64u) continue;
            const float fy = s_fade[yy];
            const int   rr = (tid >> 6) + dy + 1;
            #pragma unroll
            for (int dx = -1; dx <= 1; dx++) {
                const int xx2 = xx + dx;
                if ((unsigned)xx2 >= 64u) continue;
                const float ff = fy * s_fade[xx2];
                const float4 v = sA[(rr << 6) + ((xx2 - xs) & 63)];
                const float vx = v.x*ff, vy = v.y*ff, vz = v.z*ff, vw = v.w*ff;
                const float* wt = &s_fw2[((dy + 1)*3 + (dx + 1)) << 4];
                r0 = fmaf(wt[0],  vx, r0); r1 = fmaf(wt[1],  vx, r1);
                r2 = fmaf(wt[2],  vx, r2); r3 = fmaf(wt[3],  vx, r3);
                r0 = fmaf(wt[4],  vy, r0); r1 = fmaf(wt[5],  vy, r1);
                r2 = fmaf(wt[6],  vy, r2); r3 = fmaf(wt[7],  vy, r3);
                r0 = fmaf(wt[8],  vz, r0); r1 = fmaf(wt[9],  vz, r1);
                r2 = fmaf(wt[10], vz, r2); r3 = fmaf(wt[11], vz, r3);
                r0 = fmaf(wt[12], vw, r0); r1 = fmaf(wt[13], vw, r1);
                r2 = fmaf(wt[14], vw, r2); r3 = fmaf(wt[15], vw, r3);
            }
        }

        // damping MLP
        float u0 = s_d1b[0], u1 = s_d1b[1];
        u0 = fmaf(s_d1w[0], r0, u0); u1 = fmaf(s_d1w[4], r0, u1);
        u0 = fmaf(s_d1w[1], r1, u0); u1 = fmaf(s_d1w[5], r1, u1);
        u0 = fmaf(s_d1w[2], r2, u0); u1 = fmaf(s_d1w[6], r2, u1);
        u0 = fmaf(s_d1w[3], r3, u0); u1 = fmaf(s_d1w[7], r3, u1);
        u0 = u0 * fsig(u0);
        u1 = u1 * fsig(u1);
        const float rd0 = r0 * fsig(s_d2b[0] + s_d2w[0]*u0 + s_d2w[1]*u1);
        const float rd1 = r1 * fsig(s_d2b[1] + s_d2w[2]*u0 + s_d2w[3]*u1);
        const float rd2 = r2 * fsig(s_d2b[2] + s_d2w[4]*u0 + s_d2w[5]*u1);
        const float rd3 = r3 * fsig(s_d2b[3] + s_d2w[6]*u0 + s_d2w[7]*u1);

        w0 = fmaf(rd0, wscale, w0); w1 = fmaf(rd1, wscale, w1);
        w2 = fmaf(rd2, wscale, w2); w3 = fmaf(rd3, wscale, w3);

        if (j < 15) {
            fb0 = fmaf(rd0, 0.24f, fA0); fb1 = fmaf(rd1, 0.24f, fA1);
            fb2 = fmaf(rd2, 0.24f, fA2); fb3 = fmaf(rd3, 0.24f, fA3);
            stg4(&g_fb[(j + 1) & 1][pbase + off], make_float4(fb0, fb1, fb2, fb3));
            ys2p = ((int)(dly * 0.5f)) & 63;
            xs2p = ((int)dly)          & 63;
            csync();
        }
        decay *= 0.8f;
    }

    // ---- phase B: qkv projection from wet regs + min/max reduction -------
    float qh[4], kh[4];
    #pragma unroll
    for (int h = 0; h < 4; h++) {
        float q = s_aib[h], k = s_aib[4 + h], v = s_aib[8 + h];
        q = fmaf(s_aiw[h*4+0],     w0, q); q = fmaf(s_aiw[h*4+1],     w1, q);
        q = fmaf(s_aiw[h*4+2],     w2, q); q = fmaf(s_aiw[h*4+3],     w3, q);
        k = fmaf(s_aiw[(4+h)*4+0], w0, k); k = fmaf(s_aiw[(4+h)*4+1], w1, k);
        k = fmaf(s_aiw[(4+h)*4+2], w2, k); k = fmaf(s_aiw[(4+h)*4+3], w3, k);
        v = fmaf(s_aiw[(8+h)*4+0], w0, v); v = fmaf(s_aiw[(8+h)*4+1], w1, v);
        v = fmaf(s_aiw[(8+h)*4+2], w2, v); v = fmaf(s_aiw[(8+h)*4+3], w3, v);
        qh[h] = q; kh[h] = k;
        float2* kvp = &g_kv[((b*4 + h) << 12) + off];
        __stcg((float2*)kvp, make_float2(k, v));
    }
    // warp reduce: [0..3]=qmin [4..7]=qmax [8..11]=kmin [12..15]=kmax
    {
        float red[16];
        #pragma unroll
        for (int h = 0; h < 4; h++) {
            red[h] = qh[h]; red[4+h] = qh[h]; red[8+h] = kh[h]; red[12+h] = kh[h];
        }
        #pragma unroll
        for (int o = 16; o > 0; o >>= 1) {
            #pragma unroll
            for (int h = 0; h < 4; h++) {
                red[h]    = fminf(red[h],    __shfl_xor_sync(0xFFFFFFFFu, red[h],    o));
                red[4+h]  = fmaxf(red[4+h],  __shfl_xor_sync(0xFFFFFFFFu, red[4+h],  o));
                red[8+h]  = fminf(red[8+h],  __shfl_xor_sync(0xFFFFFFFFu, red[8+h],  o));
                red[12+h] = fmaxf(red[12+h], __shfl_xor_sync(0xFFFFFFFFu, red[12+h], o));
            }
        }
        if ((tid & 31) == 0) {
            #pragma unroll
            for (int i = 0; i < 16; i++) s_red[tid >> 5][i] = red[i];
        }
    }
    __syncthreads();
    if (tid < 16) {
        const bool ismax = (tid >> 2) & 1;
        float v = s_red[0][tid];
        #pragma unroll
        for (int wq = 1; wq < 16; wq++)
            v = ismax ? fmaxf(v, s_red[wq][tid]) : fminf(v, s_red[wq][tid]);
        g_red[b][rank][tid] = v;
    }
    csync();

    // ---- phase C: softmax output table (64 nodes/head) -------------------
    if (tid < 16) {
        const bool ismax = (tid >> 2) & 1;
        float v = __ldcg(&g_red[b][0][tid]);
        #pragma unroll
        for (int r = 1; r < 8; r++) {
            const float u = __ldcg(&g_red[b][r][tid]);
            v = ismax ? fmaxf(v, u) : fminf(v, u);
        }
        s_meta[tid] = v;
    }
    {
        const int head = rank >> 1;
        float4*       dst = (float4*)s_buf;
        const float4* src = (const float4*)&g_kv[((b*4 + head) << 12)];
        #pragma unroll
        for (int i = tid; i < 2048; i += 512) dst[i] = __ldcg(&src[i]);
        __syncthreads();

        const float amin = s_meta[head],     amax = s_meta[4 + head];
        const float kmn  = s_meta[8 + head], kmx  = s_meta[12 + head];
        const float hs   = fmaxf((amax - amin) * (1.0f/TBL_SPAN), 1e-30f);
        const int   nl   = tid >> 4;                 // 32 nodes per CTA
        const int   sl   = tid & 15;
        const int   n    = ((rank & 1) << 5) + nl;
        const float a2   = (amin + (float)(n - 1) * hs) * LOG2E;
        const float m2   = fmaxf(a2 * kmn, a2 * kmx);

        float num = 0.f, den = 0.f;
        const float2* p2 = (const float2*)s_buf + (sl << 8);
        #pragma unroll 8
        for (int jj = 0; jj < 256; jj++) {
            const float2 kv = p2[jj];
            const float  e  = fexp2(fmaf(a2, kv.x, -m2));
            num = fmaf(e, kv.y, num);
            den += e;
        }
        #pragma unroll
        for (int o = 8; o > 0; o >>= 1) {
            num += __shfl_xor_sync(0xFFFFFFFFu, num, o);
            den += __shfl_xor_sync(0xFFFFFFFFu, den, o);
        }
        if (sl == 0)
            g_tab[(b*4 + head)*TBL_N + n] = __fdividef(num, den);
    }
    csync();

    // ---- phase D: cubic Lagrange interpolation per pixel -----------------
    if (tid < 4*TBL_N) s_buf[tid] = __ldcg(&g_tab[b*4*TBL_N + tid]);
    __syncthreads();
    {
        float oh[4];
        #pragma unroll
        for (int h = 0; h < 4; h++) {
            const float amin = s_meta[h];
            const float hs   = fmaxf((s_meta[4+h] - amin) * (1.0f/TBL_SPAN), 1e-30f);
            float sr = (qh[h] - amin) * __fdividef(1.0f, hs);
            sr = fminf(fmaxf(sr, 0.0f), TBL_SPAN);
            const float fi = floorf(sr);
            const int   i0 = (int)fi;
            const float f  = sr - fi;
            const float* t = &s_buf[h*TBL_N + i0];
            const float fm1 = f + 1.0f, f1 = f - 1.0f, f2 = f - 2.0f;
            const float c0 = -f  * f1 * f2 * (1.0f/6.0f);
            const float c1 =  fm1 * f1 * f2 * 0.5f;
            const float c2 = -fm1 * f  * f2 * 0.5f;
            const float c3 =  fm1 * f  * f1 * (1.0f/6.0f);
            oh[h] = c0*t[0] + c1*t[1] + c2*t[2] + c3*t[3];
        }
        stg4(&g_o4[pbase + off], make_float4(oh[0], oh[1], oh[2], oh[3]));
    }
    csync();

    // ---- phase E1: box blur fused with attention out-projection ----------
    {
        float sx = 0.f, sy = 0.f, sz = 0.f, sw = 0.f, cnt = 0.f;
        #pragma unroll
        for (int dy = -1; dy <= 1; dy++) {
            const int yy = y + dy;
            if ((unsigned)yy >= 64u) continue;
            #pragma unroll
            for (int dx = -1; dx <= 1; dx++) {
                const int xx2 = xx + dx;
                if ((unsigned)xx2 >= 64u) continue;
                const float4 o = __ldcg(&g_o4[pbase + (yy << 6) + xx2]);
                sx += o.x; sy += o.y; sz += o.z; sw += o.w;
                cnt += 1.0f;
            }
        }
        float oc[4];
        #pragma unroll
        for (int c = 0; c < 4; c++) {
            float pr = cnt * s_aob[c];
            pr = fmaf(s_aow[c*4+0], sx, pr); pr = fmaf(s_aow[c*4+1], sy, pr);
            pr = fmaf(s_aow[c*4+2], sz, pr); pr = fmaf(s_aow[c*4+3], sw, pr);
            oc[c] = pr * (1.0f/9.0f);
        }
        stg4(&g_w34[pbase + off], make_float4(oc[0], oc[1], oc[2], oc[3]));
    }
    csync();

    // ---- phase E2: edge enhance + spatial conv + 1x1 out + mix -----------
    {
        const float4 ctr = __ldcg(&g_w34[pbase + off]);
        float n0 = 0.f, n1 = 0.f, n2 = 0.f, n3 = 0.f;
        float sf[8];
        #pragma unroll
        for (int o = 0; o < 8; o++) sf[o] = s_spb[o];
        #pragma unroll
        for (int dy = -1; dy <= 1; dy++) {
            const int yy = y + dy;
            if ((unsigned)yy >= 64u) continue;
            #pragma unroll
            for (int dx = -1; dx <= 1; dx++) {
                const int xx2 = xx + dx;
                if ((unsigned)xx2 >= 64u) continue;
                const int s2 = (yy << 6) + xx2;
                if (!(dy == 0 && dx == 0)) {
                    const float4 v = __ldcg(&g_w34[pbase + s2]);
                    n0 += v.x; n1 += v.y; n2 += v.z; n3 += v.w;
                }
                const float4 xv  = __ldcg(&g_x4[pbase + s2]);
                const int   wtap = (dy + 1)*3 + (dx + 1);
                #pragma unroll
                for (int o = 0; o < 8; o++) {
                    float a = sf[o];
                    a = fmaf(s_spw[(o*4 + 0)*9 + wtap], xv.x, a);
                    a = fmaf(s_spw[(o*4 + 1)*9 + wtap], xv.y, a);
                    a = fmaf(s_spw[(o*4 + 2)*9 + wtap], xv.z, a);
                    a = fmaf(s_spw[(o*4 + 3)*9 + wtap], xv.w, a);
                    sf[o] = a;
                }
            }
        }
        float wet4[4];
        wet4[0] = fmaf(8.0f*ctr.x - n0, 0.04f, ctr.x);
        wet4[1] = fmaf(8.0f*ctr.y - n1, 0.04f, ctr.y);
        wet4[2] = fmaf(8.0f*ctr.z - n2, 0.04f, ctr.z);
        wet4[3] = fmaf(8.0f*ctr.w - n3, 0.04f, ctr.w);

        const float xc[4] = { x0, x1, x2, x3 };
        #pragma unroll
        for (int c = 0; c < 4; c++) {
            float pr = s_ob[c];
            #pragma unroll
            for (int jq = 0; jq < 8; jq++) pr = fmaf(s_ow[c*12 + jq],     sf[jq],   pr);
            #pragma unroll
            for (int jq = 0; jq < 4; jq++) pr = fmaf(s_ow[c*12 + 8 + jq], wet4[jq], pr);
            out[((b*4 + c) << 12) + off] = fmaf(xc[c], 0.7f, 0.3f * pr);
        }
    }
}

// ---------------- launcher ---------------------------------------------------
extern "C" void kernel_launch(void* const* d_in, const int* in_sizes, int n_in,
                              void* d_out, int out_size)
{
    const float* x   = (const float*)d_in[0];
    const float* rw  = (const float*)d_in[1];
    const float* rd  = (const float*)d_in[2];
    // d_in[3] = diffusion_strength (unused by reference)
    const float* spw = (const float*)d_in[4];
    const float* spb = (const float*)d_in[5];
    const float* fw  = (const float*)d_in[6];
    const float* fb  = (const float*)d_in[7];
    const float* d1w = (const float*)d_in[8];
    const float* d1b = (const float*)d_in[9];
    const float* d2w = (const float*)d_in[10];
    const float* d2b = (const float*)d_in[11];
    const float* aiw = (const float*)d_in[12];
    const float* aib = (const float*)d_in[13];
    const float* aow = (const float*)d_in[14];
    const float* aob = (const float*)d_in[15];
    const float* ow  = (const float*)d_in[16];
    const float* ob  = (const float*)d_in[17];
    float* out = (float*)d_out;

    fused_kernel<<<dim3(8, 4), 512>>>(x, rw, rd, fw, fb, d1w, d1b, d2w, d2b,
                                      aiw, aib, aow, aob, spw, spb, ow, ob, out);
}

// round 6
// speedup vs baseline: 2.9343x; 1.3608x over previous
#include <cuda_runtime.h>

// LatentReverb fused single-kernel v2: B=4, C=4, H=W=64, NREF=16
// DECAY=0.8, WET_MIX=0.3, FEEDBACK=0.4, ROOM=0.5, HEADS=4 (head_dim=1)
// grid (8,4), cluster 8, 1024 threads/CTA (2 threads per pixel, tap-split conv)

#define LOG2E 1.4426950408889634f
#define TBL_N 64
#define TBL_SPAN 60.0f
#define PART_OFF 768   // float4 offset of conv partials inside s_buf

// ---------------- scratch (static device globals; no allocation) -------------
__device__ float4 g_fb[2][4*4096];   // ping-pong feedback state (channel-last)
__device__ float4 g_x4  [4*4096];    // x transposed to channel-last
__device__ float4 g_q4  [4*4096];    // per-pixel q (4 heads)
__device__ float2 g_kv  [16*4096];   // per (b,h): (k, v)
__device__ float  g_red [4][8][16];  // per (b, cta): 16 partial min/max values
__device__ float  g_tab [16*TBL_N]; // per (b,h): softmax-output table
__device__ float4 g_o4  [4*4096];    // attention output (4 heads / pixel)
__device__ float4 g_w34 [4*4096];    // blurred + projected wet

// ---------------- helpers ----------------------------------------------------
__device__ __forceinline__ float fexp2(float x) {
    float y;
    asm("ex2.approx.ftz.f32 %0, %1;" : "=f"(y) : "f"(x));
    return y;
}
__device__ __forceinline__ float fsig(float x) {
    return __fdividef(1.0f, 1.0f + fexp2(-LOG2E * x));
}
__device__ __forceinline__ float fadef(int i) {
    float v = 1.0f;
    if (i < 4)   v = 0.6f + (0.4f/3.0f) * (float)i;
    if (i >= 60) v = 0.6f + (0.4f/3.0f) * (float)(63 - i);
    return v;
}
__device__ __forceinline__ void csync() {
    asm volatile("barrier.cluster.arrive.aligned;" ::: "memory");
    asm volatile("barrier.cluster.wait.aligned;"   ::: "memory");
}

// ---------------- the one kernel ---------------------------------------------
__global__ void __cluster_dims__(8,1,1) __launch_bounds__(1024, 1) fused_kernel(
    const float* __restrict__ x,
    const float* __restrict__ rw,  const float* __restrict__ rd,
    const float* __restrict__ fw,  const float* __restrict__ fbias,
    const float* __restrict__ d1w, const float* __restrict__ d1b,
    const float* __restrict__ d2w, const float* __restrict__ d2b,
    const float* __restrict__ aiw, const float* __restrict__ aib,
    const float* __restrict__ aow, const float* __restrict__ aob,
    const float* __restrict__ spw, const float* __restrict__ spb,
    const float* __restrict__ ow,  const float* __restrict__ ob,
    float* __restrict__ out)
{
    // union scratch: sA staging (640 f4) + conv partials (512 f4 @PART_OFF)
    //             / phase C kv (2048 f4) / phase D table (256 f)
    __shared__ __align__(16) float s_buf[8192];
    __shared__ __align__(16) float s_fw4[144];  // [tap][ic] -> float4 over oc
    __shared__ float s_cb[4];
    __shared__ float s_d1w[8], s_d1b[2], s_d2w[8], s_d2b[4];
    __shared__ float s_rw[16], s_rd[16], s_fade[64];
    __shared__ float s_aiw[48], s_aib[12], s_aow[16], s_aob[4];
    __shared__ float s_spw[288], s_spb[8], s_ow[48], s_ob[4];
    __shared__ float s_red[16][16];
    __shared__ float s_meta[16];

    const int tid  = threadIdx.x;
    const int rank = blockIdx.x;               // cluster CTA rank
    const int b    = blockIdx.y;

    // ---- weight staging --------------------------------------------------
    if (tid < 144) {
        // s_fw4 flat idx = (tap*4 + ic)*4 + oc
        const int oc = tid & 3, ic = (tid >> 2) & 3, tap = tid >> 4;
        s_fw4[tid] = fw[(oc*4 + ic)*9 + tap];
    }
    if (tid < 4)   s_cb[tid]  = fbias[tid];
    if (tid < 8)   s_d1w[tid] = d1w[tid];
    if (tid < 2)   s_d1b[tid] = d1b[tid];
    if (tid < 8)   s_d2w[tid] = d2w[tid];
    if (tid < 4)   s_d2b[tid] = d2b[tid];
    if (tid < 16)  { s_rw[tid] = rw[tid]; s_rd[tid] = rd[tid]; }
    if (tid < 64)  s_fade[tid] = fadef(tid);
    if (tid < 48)  s_aiw[tid] = aiw[tid];
    if (tid < 12)  s_aib[tid] = aib[tid];
    if (tid < 16)  s_aow[tid] = aow[tid];
    if (tid < 4)   s_aob[tid] = aob[tid];
    {
        int i = tid; if (i < 288) s_spw[i] = spw[i];
        i = tid - 288; if (i >= 0 && i < 8)  s_spb[i] = spb[i];
        i = tid - 296; if (i >= 0 && i < 48) s_ow[i]  = ow[i];
        i = tid - 344; if (i >= 0 && i < 4)  s_ob[i]  = ob[i];
    }

    const bool low  = tid < 512;
    const int  pix  = tid & 511;
    const int  y0   = rank << 3;
    const int  y    = y0 + (pix >> 6);
    const int  xx   = pix & 63;
    const int  off  = (y << 6) + xx;
    const int  pbase = b << 12;

    // ---- phase A init ----------------------------------------------------
    float fb0 = 0.f, fb1 = 0.f, fb2 = 0.f, fb3 = 0.f;
    float w0 = 0.f, w1 = 0.f, w2 = 0.f, w3 = 0.f;
    if (low) {
        const float x0 = x[((b*4 + 0) << 12) + off];
        const float x1 = x[((b*4 + 1) << 12) + off];
        const float x2 = x[((b*4 + 2) << 12) + off];
        const float x3 = x[((b*4 + 3) << 12) + off];
        __stcg(&g_x4[pbase + off], make_float4(x0, x1, x2, x3));
        fb0 = 0.1f*x0; fb1 = 0.1f*x1; fb2 = 0.1f*x2; fb3 = 0.1f*x3;
        __stcg(&g_fb[0][pbase + off], make_float4(fb0, fb1, fb2, fb3));
    }
    __syncthreads();   // s_fade etc ready for staging
    csync();

    // ---- phase A: 16 reflections -----------------------------------------
    float4* sA     = (float4*)s_buf;
    float4* s_part = (float4*)s_buf + PART_OFF;
    const float4* fw4 = (const float4*)s_fw4;
    float decay = 1.0f;
    int ys2p = 0, xs2p = 0;
    for (int j = 0; j < 16; j++) {
        const float dly = s_rd[j] * 3.0f;          // exact small int
        const int ys = ((int)dly)          & 63;
        const int xs = ((int)(2.0f * dly)) & 63;

        // stage 10 rows: value = (fbB + 0.08*fade_src*fbB(. - s2prev)) * fade_out
        const float4* Bp = g_fb[j & 1] + pbase;
        if (tid < 640) {
            const int r = tid >> 6, px = tid & 63;
            const int srow = (y0 - 1 + r - ys) & 63;
            float4 v = __ldcg(&Bp[(srow << 6) + px]);
            if (j >= 2) {
                const float t = 0.08f * s_fade[srow] * s_fade[px];
                const float4 v2 = __ldcg(
                    &Bp[(((srow - ys2p) & 63) << 6) + ((px - xs2p) & 63)]);
                v.x = fmaf(t, v2.x, v.x); v.y = fmaf(t, v2.y, v.y);
                v.z = fmaf(t, v2.z, v.z); v.w = fmaf(t, v2.w, v.w);
            }
            const float fo = s_fade[(y0 - 1 + r) & 63] * s_fade[(px + xs) & 63];
            v.x *= fo; v.y *= fo; v.z *= fo; v.w *= fo;
            sA[tid] = v;
        }
        // low: own fbA regs (feedback incl. second roll, NO output fade)
        float fA0 = fb0, fA1 = fb1, fA2 = fb2, fA3 = fb3;
        if (low && j >= 2) {
            const float t = 0.08f * s_fade[y] * s_fade[xx];
            const float4 v2 = __ldcg(
                &Bp[(((y - ys2p) & 63) << 6) + ((xx - xs2p) & 63)]);
            fA0 = fmaf(t, v2.x, fA0); fA1 = fmaf(t, v2.y, fA1);
            fA2 = fmaf(t, v2.z, fA2); fA3 = fmaf(t, v2.w, fA3);
        }
        __syncthreads();

        // tap-split conv3x3: low = {(-1,*),(0,-1)}+bias, high = {(0,0),(0,1),(1,*)}
        float r0, r1, r2, r3;
        if (low) { r0 = s_cb[0]; r1 = s_cb[1]; r2 = s_cb[2]; r3 = s_cb[3]; }
        else     { r0 = 0.f; r1 = 0.f; r2 = 0.f; r3 = 0.f; }
        const int rbase = pix >> 6;   // local row 0..7
        #pragma unroll
        for (int t5 = 0; t5 < 5; t5++) {
            int dy, dx;
            if (low) {
                if (t5 == 4) break;
                dy = (t5 < 3) ? -1 : 0;
                dx = (t5 < 3) ? (t5 - 1) : -1;
            } else {
                dy = (t5 < 2) ? 0 : 1;
                dx = (t5 < 2) ? t5 : (t5 - 3);
            }
            const int yy = y + dy, xc = xx + dx;
            if ((unsigned)yy >= 64u || (unsigned)xc >= 64u) continue;
            const float4 v = sA[((rbase + dy + 1) << 6) + ((xc - xs) & 63)];
            const int wt = ((dy + 1)*3 + (dx + 1)) << 2;
            const float4 wa = fw4[wt + 0], wb = fw4[wt + 1];
            const float4 wc = fw4[wt + 2], wd = fw4[wt + 3];
            r0 = fmaf(wa.x, v.x, r0); r1 = fmaf(wa.y, v.x, r1);
            r2 = fmaf(wa.z, v.x, r2); r3 = fmaf(wa.w, v.x, r3);
            r0 = fmaf(wb.x, v.y, r0); r1 = fmaf(wb.y, v.y, r1);
            r2 = fmaf(wb.z, v.y, r2); r3 = fmaf(wb.w, v.y, r3);
            r0 = fmaf(wc.x, v.z, r0); r1 = fmaf(wc.y, v.z, r1);
            r2 = fmaf(wc.z, v.z, r2); r3 = fmaf(wc.w, v.z, r3);
            r0 = fmaf(wd.x, v.w, r0); r1 = fmaf(wd.y, v.w, r1);
            r2 = fmaf(wd.z, v.w, r2); r3 = fmaf(wd.w, v.w, r3);
        }
        if (!low) s_part[pix] = make_float4(r0, r1, r2, r3);
        __syncthreads();

        if (low) {
            const float4 p4 = s_part[pix];
            r0 += p4.x; r1 += p4.y; r2 += p4.z; r3 += p4.w;

            // damping MLP
            float u0 = s_d1b[0], u1 = s_d1b[1];
            u0 = fmaf(s_d1w[0], r0, u0); u1 = fmaf(s_d1w[4], r0, u1);
            u0 = fmaf(s_d1w[1], r1, u0); u1 = fmaf(s_d1w[5], r1, u1);
            u0 = fmaf(s_d1w[2], r2, u0); u1 = fmaf(s_d1w[6], r2, u1);
            u0 = fmaf(s_d1w[3], r3, u0); u1 = fmaf(s_d1w[7], r3, u1);
            u0 = u0 * fsig(u0);
            u1 = u1 * fsig(u1);
            const float rd0 = r0 * fsig(s_d2b[0] + s_d2w[0]*u0 + s_d2w[1]*u1);
            const float rd1 = r1 * fsig(s_d2b[1] + s_d2w[2]*u0 + s_d2w[3]*u1);
            const float rd2 = r2 * fsig(s_d2b[2] + s_d2w[4]*u0 + s_d2w[5]*u1);
            const float rd3 = r3 * fsig(s_d2b[3] + s_d2w[6]*u0 + s_d2w[7]*u1);

            const float wscale = fsig(s_rw[j]) * decay * 3.0f;
            w0 = fmaf(rd0, wscale, w0); w1 = fmaf(rd1, wscale, w1);
            w2 = fmaf(rd2, wscale, w2); w3 = fmaf(rd3, wscale, w3);

            if (j < 15) {
                fb0 = fmaf(rd0, 0.24f, fA0); fb1 = fmaf(rd1, 0.24f, fA1);
                fb2 = fmaf(rd2, 0.24f, fA2); fb3 = fmaf(rd3, 0.24f, fA3);
                __stcg(&g_fb[(j + 1) & 1][pbase + off],
                       make_float4(fb0, fb1, fb2, fb3));
            }
        }
        ys2p = ((int)(dly * 0.5f)) & 63;
        xs2p = ((int)dly)          & 63;
        decay *= 0.8f;
        if (j < 15) csync();
    }

    // ---- phase B: qkv projection + min/max reduction (low threads) -------
    if (low) {
        float qh[4], kh[4];
        #pragma unroll
        for (int h = 0; h < 4; h++) {
            float q = s_aib[h], k = s_aib[4 + h], v = s_aib[8 + h];
            q = fmaf(s_aiw[h*4+0],     w0, q); q = fmaf(s_aiw[h*4+1],     w1, q);
            q = fmaf(s_aiw[h*4+2],     w2, q); q = fmaf(s_aiw[h*4+3],     w3, q);
            k = fmaf(s_aiw[(4+h)*4+0], w0, k); k = fmaf(s_aiw[(4+h)*4+1], w1, k);
            k = fmaf(s_aiw[(4+h)*4+2], w2, k); k = fmaf(s_aiw[(4+h)*4+3], w3, k);
            v = fmaf(s_aiw[(8+h)*4+0], w0, v); v = fmaf(s_aiw[(8+h)*4+1], w1, v);
            v = fmaf(s_aiw[(8+h)*4+2], w2, v); v = fmaf(s_aiw[(8+h)*4+3], w3, v);
            qh[h] = q; kh[h] = k;
            __stcg(&g_kv[((b*4 + h) << 12) + off], make_float2(k, v));
        }
        __stcg(&g_q4[pbase + off], make_float4(qh[0], qh[1], qh[2], qh[3]));
        float red[16];
        #pragma unroll
        for (int h = 0; h < 4; h++) {
            red[h] = qh[h]; red[4+h] = qh[h]; red[8+h] = kh[h]; red[12+h] = kh[h];
        }
        #pragma unroll
        for (int o = 16; o > 0; o >>= 1) {
            #pragma unroll
            for (int h = 0; h < 4; h++) {
                red[h]    = fminf(red[h],    __shfl_xor_sync(0xFFFFFFFFu, red[h],    o));
                red[4+h]  = fmaxf(red[4+h],  __shfl_xor_sync(0xFFFFFFFFu, red[4+h],  o));
                red[8+h]  = fminf(red[8+h],  __shfl_xor_sync(0xFFFFFFFFu, red[8+h],  o));
                red[12+h] = fmaxf(red[12+h], __shfl_xor_sync(0xFFFFFFFFu, red[12+h], o));
            }
        }
        if ((tid & 31) == 0) {
            #pragma unroll
            for (int i = 0; i < 16; i++) s_red[tid >> 5][i] = red[i];
        }
    }
    __syncthreads();
    if (tid < 16) {
        const bool ismax = (tid >> 2) & 1;
        float v = s_red[0][tid];
        #pragma unroll
        for (int wq = 1; wq < 16; wq++)
            v = ismax ? fmaxf(v, s_red[wq][tid]) : fminf(v, s_red[wq][tid]);
        g_red[b][rank][tid] = v;
    }
    csync();

    // ---- phase C: softmax output table (64 nodes/head, conflict-free) ----
    if (tid < 16) {
        const bool ismax = (tid >> 2) & 1;
        float v = __ldcg(&g_red[b][0][tid]);
        #pragma unroll
        for (int r = 1; r < 8; r++) {
            const float u = __ldcg(&g_red[b][r][tid]);
            v = ismax ? fmaxf(v, u) : fminf(v, u);
        }
        s_meta[tid] = v;
    }
    {
        const int head = rank >> 1;
        float4*       dst = (float4*)s_buf;
        const float4* src = (const float4*)&g_kv[((b*4 + head) << 12)];
        dst[tid]        = __ldcg(&src[tid]);
        dst[tid + 1024] = __ldcg(&src[tid + 1024]);
        __syncthreads();

        const float amin = s_meta[head],     amax = s_meta[4 + head];
        const float kmn  = s_meta[8 + head], kmx  = s_meta[12 + head];
        const float hs   = fmaxf((amax - amin) * (1.0f/TBL_SPAN), 1e-30f);
        const int   lane = tid & 31;
        const int   n    = ((rank & 1) << 5) + (tid >> 5);
        const float a2   = (amin + (float)(n - 1) * hs) * LOG2E;
        const float m2   = fmaxf(a2 * kmn, a2 * kmx);

        float num = 0.f, den = 0.f;
        const float2* p2 = (const float2*)s_buf;
        #pragma unroll 8
        for (int jj = 0; jj < 128; jj++) {
            const float2 kv = p2[lane + (jj << 5)];   // conflict-free interleave
            const float  e  = fexp2(fmaf(a2, kv.x, -m2));
            num = fmaf(e, kv.y, num);
            den += e;
        }
        #pragma unroll
        for (int o = 16; o > 0; o >>= 1) {
            num += __shfl_xor_sync(0xFFFFFFFFu, num, o);
            den += __shfl_xor_sync(0xFFFFFFFFu, den, o);
        }
        if (lane == 0)
            __stcg(&g_tab[(b*4 + head)*TBL_N + n], __fdividef(num, den));
    }
    csync();

    // ---- phase D: cubic Lagrange interpolation (low threads) -------------
    if (tid < 4*TBL_N) s_buf[tid] = __ldcg(&g_tab[b*4*TBL_N + tid]);
    __syncthreads();
    if (low) {
        const float4 q4 = __ldcg(&g_q4[pbase + off]);
        const float qa[4] = { q4.x, q4.y, q4.z, q4.w };
        float oh[4];
        #pragma unroll
        for (int h = 0; h < 4; h++) {
            const float amin = s_meta[h];
            const float hs   = fmaxf((s_meta[4+h] - amin) * (1.0f/TBL_SPAN), 1e-30f);
            float sr = (qa[h] - amin) * __fdividef(1.0f, hs);
            sr = fminf(fmaxf(sr, 0.0f), TBL_SPAN);
            const float fi = floorf(sr);
            const int   i0 = (int)fi;
            const float f  = sr - fi;
            const float* t = &s_buf[h*TBL_N + i0];
            const float fm1 = f + 1.0f, f1 = f - 1.0f, f2 = f - 2.0f;
            const float c0 = -f  * f1 * f2 * (1.0f/6.0f);
            const float c1 =  fm1 * f1 * f2 * 0.5f;
            const float c2 = -fm1 * f  * f2 * 0.5f;
            const float c3 =  fm1 * f  * f1 * (1.0f/6.0f);
            oh[h] = c0*t[0] + c1*t[1] + c2*t[2] + c3*t[3];
        }
        __stcg(&g_o4[pbase + off], make_float4(oh[0], oh[1], oh[2], oh[3]));
    }
    csync();

    // ---- phase E1: box blur fused with attention out-projection ----------
    if (low) {
        float sx = 0.f, sy = 0.f, sz = 0.f, sw = 0.f, cnt = 0.f;
        #pragma unroll
        for (int dy = -1; dy <= 1; dy++) {
            const int yy = y + dy;
            if ((unsigned)yy >= 64u) continue;
            #pragma unroll
            for (int dx = -1; dx <= 1; dx++) {
                const int xc = xx + dx;
                if ((unsigned)xc >= 64u) continue;
                const float4 o = __ldcg(&g_o4[pbase + (yy << 6) + xc]);
                sx += o.x; sy += o.y; sz += o.z; sw += o.w;
                cnt += 1.0f;
            }
        }
        float oc[4];
        #pragma unroll
        for (int c = 0; c < 4; c++) {
            float pr = cnt * s_aob[c];
            pr = fmaf(s_aow[c*4+0], sx, pr); pr = fmaf(s_aow[c*4+1], sy, pr);
            pr = fmaf(s_aow[c*4+2], sz, pr); pr = fmaf(s_aow[c*4+3], sw, pr);
            oc[c] = pr * (1.0f/9.0f);
        }
        __stcg(&g_w34[pbase + off], make_float4(oc[0], oc[1], oc[2], oc[3]));
    }
    csync();

    // ---- phase E2: edge enhance + spatial conv + 1x1 out + mix -----------
    if (low) {
        const float4 ctr = __ldcg(&g_w34[pbase + off]);
        float n0 = 0.f, n1 = 0.f, n2 = 0.f, n3 = 0.f;
        float sf[8];
        float4 xctr = make_float4(0.f, 0.f, 0.f, 0.f);
        #pragma unroll
        for (int o = 0; o < 8; o++) sf[o] = s_spb[o];
        #pragma unroll
        for (int dy = -1; dy <= 1; dy++) {
            const int yy = y + dy;
            if ((unsigned)yy >= 64u) continue;
            #pragma unroll
            for (int dx = -1; dx <= 1; dx++) {
                const int xc = xx + dx;
                if ((unsigned)xc >= 64u) continue;
                const int s2 = (yy << 6) + xc;
                if (!(dy == 0 && dx == 0)) {
                    const float4 v = __ldcg(&g_w34[pbase + s2]);
                    n0 += v.x; n1 += v.y; n2 += v.z; n3 += v.w;
                }
                const float4 xv = __ldcg(&g_x4[pbase + s2]);
                if (dy == 0 && dx == 0) xctr = xv;
                const int wtap = (dy + 1)*3 + (dx + 1);
                #pragma unroll
                for (int o = 0; o < 8; o++) {
                    float a = sf[o];
                    a = fmaf(s_spw[(o*4 + 0)*9 + wtap], xv.x, a);
                    a = fmaf(s_spw[(o*4 + 1)*9 + wtap], xv.y, a);
                    a = fmaf(s_spw[(o*4 + 2)*9 + wtap], xv.z, a);
                    a = fmaf(s_spw[(o*4 + 3)*9 + wtap], xv.w, a);
                    sf[o] = a;
                }
            }
        }
        float wet4[4];
        wet4[0] = fmaf(8.0f*ctr.x - n0, 0.04f, ctr.x);
        wet4[1] = fmaf(8.0f*ctr.y - n1, 0.04f, ctr.y);
        wet4[2] = fmaf(8.0f*ctr.z - n2, 0.04f, ctr.z);
        wet4[3] = fmaf(8.0f*ctr.w - n3, 0.04f, ctr.w);

        const float xc4[4] = { xctr.x, xctr.y, xctr.z, xctr.w };
        #pragma unroll
        for (int c = 0; c < 4; c++) {
            float pr = s_ob[c];
            #pragma unroll
            for (int jq = 0; jq < 8; jq++) pr = fmaf(s_ow[c*12 + jq],     sf[jq],   pr);
            #pragma unroll
            for (int jq = 0; jq < 4; jq++) pr = fmaf(s_ow[c*12 + 8 + jq], wet4[jq], pr);
            out[((b*4 + c) << 12) + off] = fmaf(xc4[c], 0.7f, 0.3f * pr);
        }
    }
}

// ---------------- launcher ---------------------------------------------------
extern "C" void kernel_launch(void* const* d_in, const int* in_sizes, int n_in,
                              void* d_out, int out_size)
{
    const float* x   = (const float*)d_in[0];
    const float* rw  = (const float*)d_in[1];
    const float* rd  = (const float*)d_in[2];
    // d_in[3] = diffusion_strength (unused by reference)
    const float* spw = (const float*)d_in[4];
    const float* spb = (const float*)d_in[5];
    const float* fw  = (const float*)d_in[6];
    const float* fb  = (const float*)d_in[7];
    const float* d1w = (const float*)d_in[8];
    const float* d1b = (const float*)d_in[9];
    const float* d2w = (const float*)d_in[10];
    const float* d2b = (const float*)d_in[11];
    const float* aiw = (const float*)d_in[12];
    const float* aib = (const float*)d_in[13];
    const float* aow = (const float*)d_in[14];
    const float* aob = (const float*)d_in[15];
    const float* ow  = (const float*)d_in[16];
    const float* ob  = (const float*)d_in[17];
    float* out = (float*)d_out;

    fused_kernel<<<dim3(8, 4), 1024>>>(x, rw, rd, fw, fb, d1w, d1b, d2w, d2b,
                                       aiw, aib, aow, aob, spw, spb, ow, ob, out);
}

// round 8
// speedup vs baseline: 4.5158x; 1.5390x over previous
#include <cuda_runtime.h>

// LatentReverb fused single-kernel v3: B=4, C=4, H=W=64, NREF=16
// DECAY=0.8, WET_MIX=0.3, FEEDBACK=0.4, ROOM=0.5, HEADS=4 (head_dim=1)
// Primary:  grid (16,4), cluster 16 (nonportable), 512 thr/CTA, 4 rows/CTA.
// Fallback: grid (8,4),  cluster 8,               1024 thr/CTA, 8 rows/CTA.

#define LOG2E 1.4426950408889634f

// ---------------- scratch (static device globals; no allocation) -------------
__device__ float4 g_fb[2][4*4096];   // ping-pong feedback state (channel-last)
__device__ float4 g_x4  [4*4096];    // x transposed to channel-last
__device__ float4 g_q4  [4*4096];    // per-pixel q (4 heads)
__device__ float2 g_kv  [16*4096];   // per (b,h): (k, v)
__device__ float  g_red [4][16][16]; // per (b, cta): 16 partial min/max values
__device__ float  g_tab [1024];      // per (b,h): softmax-output table
__device__ float4 g_o4  [4*4096];    // (fallback only)
__device__ float4 g_w34 [4*4096];    // (fallback only)

// ---------------- helpers ----------------------------------------------------
__device__ __forceinline__ float fexp2(float x) {
    float y;
    asm("ex2.approx.ftz.f32 %0, %1;" : "=f"(y) : "f"(x));
    return y;
}
__device__ __forceinline__ float fsig(float x) {
    return __fdividef(1.0f, 1.0f + fexp2(-LOG2E * x));
}
__device__ __forceinline__ float fadef(int i) {
    float v = 1.0f;
    if (i < 4)   v = 0.6f + (0.4f/3.0f) * (float)i;
    if (i >= 60) v = 0.6f + (0.4f/3.0f) * (float)(63 - i);
    return v;
}
__device__ __forceinline__ void csync() {
    asm volatile("barrier.cluster.arrive.aligned;" ::: "memory");
    asm volatile("barrier.cluster.wait.aligned;"   ::: "memory");
}

// =============================================================================
// PRIMARY kernel: cluster 16, 512 threads, 4 rows/CTA, TBL_N=32 span 28
// =============================================================================
__global__ void __launch_bounds__(512, 1) fused16(
    const float* __restrict__ x,
    const float* __restrict__ rw,  const float* __restrict__ rd,
    const float* __restrict__ fw,  const float* __restrict__ fbias,
    const float* __restrict__ d1w, const float* __restrict__ d1b,
    const float* __restrict__ d2w, const float* __restrict__ d2b,
    const float* __restrict__ aiw, const float* __restrict__ aib,
    const float* __restrict__ aow, const float* __restrict__ aob,
    const float* __restrict__ spw, const float* __restrict__ spb,
    const float* __restrict__ ow,  const float* __restrict__ ob,
    float* __restrict__ out)
{
    // unioned scratch:
    //  A: sA f4[0..383] staging, s_part f4[384..639]
    //  C: kv f4[0..2047]
    //  D/E: s_o f4[0..511], s_w34e f4[512..895]
    __shared__ __align__(16) float s_buf[8192];
    __shared__ __align__(16) float s_fw4[144];  // [tap][ic] float4 over oc
    __shared__ float s_cb[4];
    __shared__ float s_d1w[8], s_d1b[2], s_d2w[8], s_d2b[4];
    __shared__ float s_rw[16], s_rd[16], s_fade[64];
    __shared__ float s_aiw[48], s_aib[12], s_aow[16], s_aob[4];
    __shared__ float s_spw[288], s_spb[8], s_ow[48], s_ob[4];
    __shared__ float s_red[16][16];
    __shared__ float s_meta[16];
    __shared__ float s_tab[128];

    const int tid  = threadIdx.x;
    const int rank = blockIdx.x;               // cluster rank 0..15
    const int b    = blockIdx.y;

    if (tid < 144) {
        const int oc = tid & 3, ic = (tid >> 2) & 3, tap = tid >> 4;
        s_fw4[tid] = fw[(oc*4 + ic)*9 + tap];
    }
    if (tid < 4)   s_cb[tid]  = fbias[tid];
    if (tid < 8)   s_d1w[tid] = d1w[tid];
    if (tid < 2)   s_d1b[tid] = d1b[tid];
    if (tid < 8)   s_d2w[tid] = d2w[tid];
    if (tid < 4)   s_d2b[tid] = d2b[tid];
    if (tid < 16)  { s_rw[tid] = rw[tid]; s_rd[tid] = rd[tid]; }
    if (tid < 64)  s_fade[tid] = fadef(tid);
    if (tid < 48)  s_aiw[tid] = aiw[tid];
    if (tid < 12)  s_aib[tid] = aib[tid];
    if (tid < 16)  s_aow[tid] = aow[tid];
    if (tid < 4)   s_aob[tid] = aob[tid];
    {
        int i = tid; if (i < 288) s_spw[i] = spw[i];
        i = tid - 288; if (i >= 0 && i < 8)  s_spb[i] = spb[i];
        i = tid - 296; if (i >= 0 && i < 48) s_ow[i]  = ow[i];
        i = tid - 344; if (i >= 0 && i < 4)  s_ob[i]  = ob[i];
    }

    const bool low  = tid < 256;
    const int  pix  = tid & 255;
    const int  y0   = rank << 2;
    const int  y    = y0 + (pix >> 6);
    const int  xx   = pix & 63;
    const int  off  = (y << 6) + xx;
    const int  pbase = b << 12;

    // ---- init: fb = 0.1*x; x to channel-last -----------------------------
    float fb0 = 0.f, fb1 = 0.f, fb2 = 0.f, fb3 = 0.f;
    float w0 = 0.f, w1 = 0.f, w2 = 0.f, w3 = 0.f;
    if (low) {
        const float x0 = x[((b*4 + 0) << 12) + off];
        const float x1 = x[((b*4 + 1) << 12) + off];
        const float x2 = x[((b*4 + 2) << 12) + off];
        const float x3 = x[((b*4 + 3) << 12) + off];
        __stcg(&g_x4[pbase + off], make_float4(x0, x1, x2, x3));
        fb0 = 0.1f*x0; fb1 = 0.1f*x1; fb2 = 0.1f*x2; fb3 = 0.1f*x3;
        __stcg(&g_fb[0][pbase + off], make_float4(fb0, fb1, fb2, fb3));
    }
    __syncthreads();
    csync();

    // ---- phase A: 16 reflections, one csync each -------------------------
    float4* sA     = (float4*)s_buf;           // 6 rows x 64
    float4* s_part = (float4*)s_buf + 384;
    const float4* fw4 = (const float4*)s_fw4;
    float decay = 1.0f;
    int ys2p = 0, xs2p = 0;
    for (int j = 0; j < 16; j++) {
        const float dly = s_rd[j] * 3.0f;
        const int ys = ((int)dly)          & 63;
        const int xs = ((int)(2.0f * dly)) & 63;

        const float4* Bp = g_fb[j & 1] + pbase;
        if (tid < 384) {
            const int r = tid >> 6, px = tid & 63;
            const int srow = (y0 - 1 + r - ys) & 63;
            float4 v = __ldcg(&Bp[(srow << 6) + px]);
            if (j >= 2) {
                const float t = 0.08f * s_fade[srow] * s_fade[px];
                const float4 v2 = __ldcg(
                    &Bp[(((srow - ys2p) & 63) << 6) + ((px - xs2p) & 63)]);
                v.x = fmaf(t, v2.x, v.x); v.y = fmaf(t, v2.y, v.y);
                v.z = fmaf(t, v2.z, v.z); v.w = fmaf(t, v2.w, v.w);
            }
            const float fo = s_fade[(y0 - 1 + r) & 63] * s_fade[(px + xs) & 63];
            v.x *= fo; v.y *= fo; v.z *= fo; v.w *= fo;
            sA[tid] = v;
        }
        float fA0 = fb0, fA1 = fb1, fA2 = fb2, fA3 = fb3;
        if (low && j >= 2) {
            const float t = 0.08f * s_fade[y] * s_fade[xx];
            const float4 v2 = __ldcg(
                &Bp[(((y - ys2p) & 63) << 6) + ((xx - xs2p) & 63)]);
            fA0 = fmaf(t, v2.x, fA0); fA1 = fmaf(t, v2.y, fA1);
            fA2 = fmaf(t, v2.z, fA2); fA3 = fmaf(t, v2.w, fA3);
        }
        __syncthreads();

        // tap-split conv3x3
        float r0, r1, r2, r3;
        if (low) { r0 = s_cb[0]; r1 = s_cb[1]; r2 = s_cb[2]; r3 = s_cb[3]; }
        else     { r0 = 0.f; r1 = 0.f; r2 = 0.f; r3 = 0.f; }
        const int rbase = pix >> 6;
        #pragma unroll
        for (int t5 = 0; t5 < 5; t5++) {
            int dy, dx;
            if (low) {
                if (t5 == 4) break;
                dy = (t5 < 3) ? -1 : 0;
                dx = (t5 < 3) ? (t5 - 1) : -1;
            } else {
                dy = (t5 < 2) ? 0 : 1;
                dx = (t5 < 2) ? t5 : (t5 - 3);
            }
            const int yy = y + dy, xc = xx + dx;
            if ((unsigned)yy >= 64u || (unsigned)xc >= 64u) continue;
            const float4 v = sA[((rbase + dy + 1) << 6) + ((xc - xs) & 63)];
            const int wt = ((dy + 1)*3 + (dx + 1)) << 2;
            const float4 wa = fw4[wt + 0], wb = fw4[wt + 1];
            const float4 wc = fw4[wt + 2], wd = fw4[wt + 3];
            r0 = fmaf(wa.x, v.x, r0); r1 = fmaf(wa.y, v.x, r1);
            r2 = fmaf(wa.z, v.x, r2); r3 = fmaf(wa.w, v.x, r3);
            r0 = fmaf(wb.x, v.y, r0); r1 = fmaf(wb.y, v.y, r1);
            r2 = fmaf(wb.z, v.y, r2); r3 = fmaf(wb.w, v.y, r3);
            r0 = fmaf(wc.x, v.z, r0); r1 = fmaf(wc.y, v.z, r1);
            r2 = fmaf(wc.z, v.z, r2); r3 = fmaf(wc.w, v.z, r3);
            r0 = fmaf(wd.x, v.w, r0); r1 = fmaf(wd.y, v.w, r1);
            r2 = fmaf(wd.z, v.w, r2); r3 = fmaf(wd.w, v.w, r3);
        }
        if (!low) s_part[pix] = make_float4(r0, r1, r2, r3);
        __syncthreads();

        if (low) {
            const float4 p4 = s_part[pix];
            r0 += p4.x; r1 += p4.y; r2 += p4.z; r3 += p4.w;

            float u0 = s_d1b[0], u1 = s_d1b[1];
            u0 = fmaf(s_d1w[0], r0, u0); u1 = fmaf(s_d1w[4], r0, u1);
            u0 = fmaf(s_d1w[1], r1, u0); u1 = fmaf(s_d1w[5], r1, u1);
            u0 = fmaf(s_d1w[2], r2, u0); u1 = fmaf(s_d1w[6], r2, u1);
            u0 = fmaf(s_d1w[3], r3, u0); u1 = fmaf(s_d1w[7], r3, u1);
            u0 = u0 * fsig(u0);
            u1 = u1 * fsig(u1);
            const float rd0 = r0 * fsig(s_d2b[0] + s_d2w[0]*u0 + s_d2w[1]*u1);
            const float rd1 = r1 * fsig(s_d2b[1] + s_d2w[2]*u0 + s_d2w[3]*u1);
            const float rd2 = r2 * fsig(s_d2b[2] + s_d2w[4]*u0 + s_d2w[5]*u1);
            const float rd3 = r3 * fsig(s_d2b[3] + s_d2w[6]*u0 + s_d2w[7]*u1);

            const float wscale = fsig(s_rw[j]) * decay * 3.0f;
            w0 = fmaf(rd0, wscale, w0); w1 = fmaf(rd1, wscale, w1);
            w2 = fmaf(rd2, wscale, w2); w3 = fmaf(rd3, wscale, w3);

            if (j < 15) {
                fb0 = fmaf(rd0, 0.24f, fA0); fb1 = fmaf(rd1, 0.24f, fA1);
                fb2 = fmaf(rd2, 0.24f, fA2); fb3 = fmaf(rd3, 0.24f, fA3);
                __stcg(&g_fb[(j + 1) & 1][pbase + off],
                       make_float4(fb0, fb1, fb2, fb3));
            }
        }
        ys2p = ((int)(dly * 0.5f)) & 63;
        xs2p = ((int)dly)          & 63;
        decay *= 0.8f;
        if (j < 15) csync();
    }

    // ---- phase B: qkv + min/max reduction --------------------------------
    if (low) {
        float qh[4], kh[4];
        #pragma unroll
        for (int h = 0; h < 4; h++) {
            float q = s_aib[h], k = s_aib[4 + h], v = s_aib[8 + h];
            q = fmaf(s_aiw[h*4+0],     w0, q); q = fmaf(s_aiw[h*4+1],     w1, q);
            q = fmaf(s_aiw[h*4+2],     w2, q); q = fmaf(s_aiw[h*4+3],     w3, q);
            k = fmaf(s_aiw[(4+h)*4+0], w0, k); k = fmaf(s_aiw[(4+h)*4+1], w1, k);
            k = fmaf(s_aiw[(4+h)*4+2], w2, k); k = fmaf(s_aiw[(4+h)*4+3], w3, k);
            v = fmaf(s_aiw[(8+h)*4+0], w0, v); v = fmaf(s_aiw[(8+h)*4+1], w1, v);
            v = fmaf(s_aiw[(8+h)*4+2], w2, v); v = fmaf(s_aiw[(8+h)*4+3], w3, v);
            qh[h] = q; kh[h] = k;
            __stcg(&g_kv[((b*4 + h) << 12) + off], make_float2(k, v));
        }
        __stcg(&g_q4[pbase + off], make_float4(qh[0], qh[1], qh[2], qh[3]));
        float red[16];
        #pragma unroll
        for (int h = 0; h < 4; h++) {
            red[h] = qh[h]; red[4+h] = qh[h]; red[8+h] = kh[h]; red[12+h] = kh[h];
        }
        #pragma unroll
        for (int o = 16; o > 0; o >>= 1) {
            #pragma unroll
            for (int h = 0; h < 4; h++) {
                red[h]    = fminf(red[h],    __shfl_xor_sync(0xFFFFFFFFu, red[h],    o));
                red[4+h]  = fmaxf(red[4+h],  __shfl_xor_sync(0xFFFFFFFFu, red[4+h],  o));
                red[8+h]  = fminf(red[8+h],  __shfl_xor_sync(0xFFFFFFFFu, red[8+h],  o));
                red[12+h] = fmaxf(red[12+h], __shfl_xor_sync(0xFFFFFFFFu, red[12+h], o));
            }
        }
        if ((tid & 31) == 0) {
            #pragma unroll
            for (int i = 0; i < 16; i++) s_red[tid >> 5][i] = red[i];
        }
    }
    __syncthreads();
    if (tid < 16) {
        const bool ismax = (tid >> 2) & 1;
        float v = s_red[0][tid];
        #pragma unroll
        for (int wq = 1; wq < 8; wq++)
            v = ismax ? fmaxf(v, s_red[wq][tid]) : fminf(v, s_red[wq][tid]);
        g_red[b][rank][tid] = v;
    }
    csync();

    // ---- phase C: softmax table, 32 nodes/head, 8 nodes/CTA --------------
    if (tid < 16) {
        const bool ismax = (tid >> 2) & 1;
        float v = __ldcg(&g_red[b][0][tid]);
        #pragma unroll
        for (int r = 1; r < 16; r++) {
            const float u = __ldcg(&g_red[b][r][tid]);
            v = ismax ? fmaxf(v, u) : fminf(v, u);
        }
        s_meta[tid] = v;
    }
    {
        const int head = rank >> 2;
        float4*       dst = (float4*)s_buf;
        const float4* src = (const float4*)&g_kv[((b*4 + head) << 12)];
        #pragma unroll
        for (int k4 = 0; k4 < 4; k4++)
            dst[tid + (k4 << 9)] = __ldcg(&src[tid + (k4 << 9)]);
        __syncthreads();

        const float amin = s_meta[head],     amax = s_meta[4 + head];
        const float kmn  = s_meta[8 + head], kmx  = s_meta[12 + head];
        const float hs   = fmaxf((amax - amin) * (1.0f/28.0f), 1e-30f);
        const int   nloc = tid >> 6;                 // 0..7
        const int   l64  = tid & 63;
        const int   n    = ((rank & 3) << 3) + nloc; // 0..31
        const float a2   = (amin + (float)(n - 1) * hs) * LOG2E;
        const float m2   = fmaxf(a2 * kmn, a2 * kmx);

        float num = 0.f, den = 0.f;
        const float2* p2 = (const float2*)s_buf;
        #pragma unroll 8
        for (int jj = 0; jj < 64; jj++) {
            const float2 kv = p2[l64 + (jj << 6)];
            const float  e  = fexp2(fmaf(a2, kv.x, -m2));
            num = fmaf(e, kv.y, num);
            den += e;
        }
        #pragma unroll
        for (int o = 16; o > 0; o >>= 1) {
            num += __shfl_xor_sync(0xFFFFFFFFu, num, o);
            den += __shfl_xor_sync(0xFFFFFFFFu, den, o);
        }
        if ((tid & 31) == 0) {
            s_red[tid >> 5][0] = num;
            s_red[tid >> 5][1] = den;
        }
        __syncthreads();
        if (tid < 8) {
            const float nm = s_red[2*tid][0] + s_red[2*tid + 1][0];
            const float dn = s_red[2*tid][1] + s_red[2*tid + 1][1];
            __stcg(&g_tab[(b*4 + head)*32 + ((rank & 3) << 3) + tid],
                   __fdividef(nm, dn));
        }
    }
    csync();

    // ---- phase D: interp o for 8 rows (own 4 + 2-row halos) into SMEM ----
    if (tid < 128) s_tab[tid] = __ldcg(&g_tab[b*128 + tid]);
    __syncthreads();
    float4* s_o = (float4*)s_buf;              // [8][64]
    {
        const int erow = tid >> 6, col = tid & 63;
        const int ry   = y0 - 2 + erow;
        float4 ov = make_float4(0.f, 0.f, 0.f, 0.f);
        if ((unsigned)ry < 64u) {
            const float4 q4 = __ldcg(&g_q4[pbase + (ry << 6) + col]);
            const float qa[4] = { q4.x, q4.y, q4.z, q4.w };
            float oh[4];
            #pragma unroll
            for (int h = 0; h < 4; h++) {
                const float amin = s_meta[h];
                const float hs = fmaxf((s_meta[4+h] - amin)*(1.0f/28.0f), 1e-30f);
                float sr = (qa[h] - amin) * __fdividef(1.0f, hs);
                sr = fminf(fmaxf(sr, 0.0f), 28.0f);
                const float fi = floorf(sr);
                const int   i0 = (int)fi;
                const float f  = sr - fi;
                const float* t = &s_tab[(h << 5) + i0];
                const float fm1 = f + 1.0f, f1 = f - 1.0f, f2 = f - 2.0f;
                const float c0 = -f  * f1 * f2 * (1.0f/6.0f);
                const float c1 =  fm1 * f1 * f2 * 0.5f;
                const float c2 = -fm1 * f  * f2 * 0.5f;
                const float c3 =  fm1 * f  * f1 * (1.0f/6.0f);
                oh[h] = c0*t[0] + c1*t[1] + c2*t[2] + c3*t[3];
            }
            ov = make_float4(oh[0], oh[1], oh[2], oh[3]);
        }
        s_o[tid] = ov;
    }
    __syncthreads();

    // ---- phase E1: box blur + attn out-projection for 6 rows into SMEM ---
    float4* s_w34e = (float4*)s_buf + 512;     // [6][64]
    if (tid < 384) {
        const int brow = tid >> 6, col = tid & 63;
        const int row  = y0 - 1 + brow;
        if ((unsigned)row < 64u) {
            float sx = 0.f, sy = 0.f, sz = 0.f, sw = 0.f, cnt = 0.f;
            #pragma unroll
            for (int dy = -1; dy <= 1; dy++) {
                const int r2 = row + dy;
                if ((unsigned)r2 >= 64u) continue;
                const int er = brow + 1 + dy;
                #pragma unroll
                for (int dx = -1; dx <= 1; dx++) {
                    const int c2 = col + dx;
                    if ((unsigned)c2 >= 64u) continue;
                    const float4 o = s_o[(er << 6) + c2];
                    sx += o.x; sy += o.y; sz += o.z; sw += o.w;
                    cnt += 1.0f;
                }
            }
            float oc[4];
            #pragma unroll
            for (int c = 0; c < 4; c++) {
                float pr = cnt * s_aob[c];
                pr = fmaf(s_aow[c*4+0], sx, pr); pr = fmaf(s_aow[c*4+1], sy, pr);
                pr = fmaf(s_aow[c*4+2], sz, pr); pr = fmaf(s_aow[c*4+3], sw, pr);
                oc[c] = pr * (1.0f/9.0f);
            }
            s_w34e[tid] = make_float4(oc[0], oc[1], oc[2], oc[3]);
        }
    }
    __syncthreads();

    // ---- phase E2: edge enhance + spatial conv + 1x1 out + mix -----------
    if (low) {
        const int lrow = pix >> 6;
        const float4 ctr = s_w34e[((lrow + 1) << 6) + xx];
        float n0 = 0.f, n1 = 0.f, n2 = 0.f, n3 = 0.f;
        float sf[8];
        float4 xctr = make_float4(0.f, 0.f, 0.f, 0.f);
        #pragma unroll
        for (int o = 0; o < 8; o++) sf[o] = s_spb[o];
        #pragma unroll
        for (int dy = -1; dy <= 1; dy++) {
            const int yy = y + dy;
            if ((unsigned)yy >= 64u) continue;
            const int wr = lrow + 1 + dy;
            #pragma unroll
            for (int dx = -1; dx <= 1; dx++) {
                const int xc = xx + dx;
                if ((unsigned)xc >= 64u) continue;
                if (!(dy == 0 && dx == 0)) {
                    const float4 v = s_w34e[(wr << 6) + xc];
                    n0 += v.x; n1 += v.y; n2 += v.z; n3 += v.w;
                }
                const float4 xv = __ldcg(&g_x4[pbase + (yy << 6) + xc]);
                if (dy == 0 && dx == 0) xctr = xv;
                const int wtap = (dy + 1)*3 + (dx + 1);
                #pragma unroll
                for (int o = 0; o < 8; o++) {
                    float a = sf[o];
                    a = fmaf(s_spw[(o*4 + 0)*9 + wtap], xv.x, a);
                    a = fmaf(s_spw[(o*4 + 1)*9 + wtap], xv.y, a);
                    a = fmaf(s_spw[(o*4 + 2)*9 + wtap], xv.z, a);
                    a = fmaf(s_spw[(o*4 + 3)*9 + wtap], xv.w, a);
                    sf[o] = a;
                }
            }
        }
        float wet4[4];
        wet4[0] = fmaf(8.0f*ctr.x - n0, 0.04f, ctr.x);
        wet4[1] = fmaf(8.0f*ctr.y - n1, 0.04f, ctr.y);
        wet4[2] = fmaf(8.0f*ctr.z - n2, 0.04f, ctr.z);
        wet4[3] = fmaf(8.0f*ctr.w - n3, 0.04f, ctr.w);

        const float xc4[4] = { xctr.x, xctr.y, xctr.z, xctr.w };
        #pragma unroll
        for (int c = 0; c < 4; c++) {
            float pr = s_ob[c];
            #pragma unroll
            for (int jq = 0; jq < 8; jq++) pr = fmaf(s_ow[c*12 + jq],     sf[jq],   pr);
            #pragma unroll
            for (int jq = 0; jq < 4; jq++) pr = fmaf(s_ow[c*12 + 8 + jq], wet4[jq], pr);
            out[((b*4 + c) << 12) + off] = fmaf(xc4[c], 0.7f, 0.3f * pr);
        }
    }
}

// =============================================================================
// FALLBACK kernel: proven R6 config (cluster 8, 1024 thr, TBL 64 span 60)
// =============================================================================
__global__ void __cluster_dims__(8,1,1) __launch_bounds__(1024, 1) fused8(
    const float* __restrict__ x,
    const float* __restrict__ rw,  const float* __restrict__ rd,
    const float* __restrict__ fw,  const float* __restrict__ fbias,
    const float* __restrict__ d1w, const float* __restrict__ d1b,
    const float* __restrict__ d2w, const float* __restrict__ d2b,
    const float* __restrict__ aiw, const float* __restrict__ aib,
    const float* __restrict__ aow, const float* __restrict__ aob,
    const float* __restrict__ spw, const float* __restrict__ spb,
    const float* __restrict__ ow,  const float* __restrict__ ob,
    float* __restrict__ out)
{
    __shared__ __align__(16) float s_buf[8192];
    __shared__ __align__(16) float s_fw4[144];
    __shared__ float s_cb[4];
    __shared__ float s_d1w[8], s_d1b[2], s_d2w[8], s_d2b[4];
    __shared__ float s_rw[16], s_rd[16], s_fade[64];
    __shared__ float s_aiw[48], s_aib[12], s_aow[16], s_aob[4];
    __shared__ float s_spw[288], s_spb[8], s_ow[48], s_ob[4];
    __shared__ float s_red[16][16];
    __shared__ float s_meta[16];

    const int tid  = threadIdx.x;
    const int rank = blockIdx.x;
    const int b    = blockIdx.y;

    if (tid < 144) {
        const int oc = tid & 3, ic = (tid >> 2) & 3, tap = tid >> 4;
        s_fw4[tid] = fw[(oc*4 + ic)*9 + tap];
    }
    if (tid < 4)   s_cb[tid]  = fbias[tid];
    if (tid < 8)   s_d1w[tid] = d1w[tid];
    if (tid < 2)   s_d1b[tid] = d1b[tid];
    if (tid < 8)   s_d2w[tid] = d2w[tid];
    if (tid < 4)   s_d2b[tid] = d2b[tid];
    if (tid < 16)  { s_rw[tid] = rw[tid]; s_rd[tid] = rd[tid]; }
    if (tid < 64)  s_fade[tid] = fadef(tid);
    if (tid < 48)  s_aiw[tid] = aiw[tid];
    if (tid < 12)  s_aib[tid] = aib[tid];
    if (tid < 16)  s_aow[tid] = aow[tid];
    if (tid < 4)   s_aob[tid] = aob[tid];
    {
        int i = tid; if (i < 288) s_spw[i] = spw[i];
        i = tid - 288; if (i >= 0 && i < 8)  s_spb[i] = spb[i];
        i = tid - 296; if (i >= 0 && i < 48) s_ow[i]  = ow[i];
        i = tid - 344; if (i >= 0 && i < 4)  s_ob[i]  = ob[i];
    }

    const bool low  = tid < 512;
    const int  pix  = tid & 511;
    const int  y0   = rank << 3;
    const int  y    = y0 + (pix >> 6);
    const int  xx   = pix & 63;
    const int  off  = (y << 6) + xx;
    const int  pbase = b << 12;

    float fb0 = 0.f, fb1 = 0.f, fb2 = 0.f, fb3 = 0.f;
    float w0 = 0.f, w1 = 0.f, w2 = 0.f, w3 = 0.f;
    if (low) {
        const float x0 = x[((b*4 + 0) << 12) + off];
        const float x1 = x[((b*4 + 1) << 12) + off];
        const float x2 = x[((b*4 + 2) << 12) + off];
        const float x3 = x[((b*4 + 3) << 12) + off];
        __stcg(&g_x4[pbase + off], make_float4(x0, x1, x2, x3));
        fb0 = 0.1f*x0; fb1 = 0.1f*x1; fb2 = 0.1f*x2; fb3 = 0.1f*x3;
        __stcg(&g_fb[0][pbase + off], make_float4(fb0, fb1, fb2, fb3));
    }
    __syncthreads();
    csync();

    float4* sA     = (float4*)s_buf;
    float4* s_part = (float4*)s_buf + 768;
    const float4* fw4 = (const float4*)s_fw4;
    float decay = 1.0f;
    int ys2p = 0, xs2p = 0;
    for (int j = 0; j < 16; j++) {
        const float dly = s_rd[j] * 3.0f;
        const int ys = ((int)dly)          & 63;
        const int xs = ((int)(2.0f * dly)) & 63;

        const float4* Bp = g_fb[j & 1] + pbase;
        if (tid < 640) {
            const int r = tid >> 6, px = tid & 63;
            const int srow = (y0 - 1 + r - ys) & 63;
            float4 v = __ldcg(&Bp[(srow << 6) + px]);
            if (j >= 2) {
                const float t = 0.08f * s_fade[srow] * s_fade[px];
                const float4 v2 = __ldcg(
                    &Bp[(((srow - ys2p) & 63) << 6) + ((px - xs2p) & 63)]);
                v.x = fmaf(t, v2.x, v.x); v.y = fmaf(t, v2.y, v.y);
                v.z = fmaf(t, v2.z, v.z); v.w = fmaf(t, v2.w, v.w);
            }
            const float fo = s_fade[(y0 - 1 + r) & 63] * s_fade[(px + xs) & 63];
            v.x *= fo; v.y *= fo; v.z *= fo; v.w *= fo;
            sA[tid] = v;
        }
        float fA0 = fb0, fA1 = fb1, fA2 = fb2, fA3 = fb3;
        if (low && j >= 2) {
            const float t = 0.08f * s_fade[y] * s_fade[xx];
            const float4 v2 = __ldcg(
                &Bp[(((y - ys2p) & 63) << 6) + ((xx - xs2p) & 63)]);
            fA0 = fmaf(t, v2.x, fA0); fA1 = fmaf(t, v2.y, fA1);
            fA2 = fmaf(t, v2.z, fA2); fA3 = fmaf(t, v2.w, fA3);
        }
        __syncthreads();

        float r0, r1, r2, r3;
        if (low) { r0 = s_cb[0]; r1 = s_cb[1]; r2 = s_cb[2]; r3 = s_cb[3]; }
        else     { r0 = 0.f; r1 = 0.f; r2 = 0.f; r3 = 0.f; }
        const int rbase = pix >> 6;
        #pragma unroll
        for (int t5 = 0; t5 < 5; t5++) {
            int dy, dx;
            if (low) {
                if (t5 == 4) break;
                dy = (t5 < 3) ? -1 : 0;
                dx = (t5 < 3) ? (t5 - 1) : -1;
            } else {
                dy = (t5 < 2) ? 0 : 1;
                dx = (t5 < 2) ? t5 : (t5 - 3);
            }
            const int yy = y + dy, xc = xx + dx;
            if ((unsigned)yy >= 64u || (unsigned)xc >= 64u) continue;
            const float4 v = sA[((rbase + dy + 1) << 6) + ((xc - xs) & 63)];
            const int wt = ((dy + 1)*3 + (dx + 1)) << 2;
            const float4 wa = fw4[wt + 0], wb = fw4[wt + 1];
            const float4 wc = fw4[wt + 2], wd = fw4[wt + 3];
            r0 = fmaf(wa.x, v.x, r0); r1 = fmaf(wa.y, v.x, r1);
            r2 = fmaf(wa.z, v.x, r2); r3 = fmaf(wa.w, v.x, r3);
            r0 = fmaf(wb.x, v.y, r0); r1 = fmaf(wb.y, v.y, r1);
            r2 = fmaf(wb.z, v.y, r2); r3 = fmaf(wb.w, v.y, r3);
            r0 = fmaf(wc.x, v.z, r0); r1 = fmaf(wc.y, v.z, r1);
            r2 = fmaf(wc.z, v.z, r2); r3 = fmaf(wc.w, v.z, r3);
            r0 = fmaf(wd.x, v.w, r0); r1 = fmaf(wd.y, v.w, r1);
            r2 = fmaf(wd.z, v.w, r2); r3 = fmaf(wd.w, v.w, r3);
        }
        if (!low) s_part[pix] = make_float4(r0, r1, r2, r3);
        __syncthreads();

        if (low) {
            const float4 p4 = s_part[pix];
            r0 += p4.x; r1 += p4.y; r2 += p4.z; r3 += p4.w;

            float u0 = s_d1b[0], u1 = s_d1b[1];
            u0 = fmaf(s_d1w[0], r0, u0); u1 = fmaf(s_d1w[4], r0, u1);
            u0 = fmaf(s_d1w[1], r1, u0); u1 = fmaf(s_d1w[5], r1, u1);
            u0 = fmaf(s_d1w[2], r2, u0); u1 = fmaf(s_d1w[6], r2, u1);
            u0 = fmaf(s_d1w[3], r3, u0); u1 = fmaf(s_d1w[7], r3, u1);
            u0 = u0 * fsig(u0);
            u1 = u1 * fsig(u1);
            const float rd0 = r0 * fsig(s_d2b[0] + s_d2w[0]*u0 + s_d2w[1]*u1);
            const float rd1 = r1 * fsig(s_d2b[1] + s_d2w[2]*u0 + s_d2w[3]*u1);
            const float rd2 = r2 * fsig(s_d2b[2] + s_d2w[4]*u0 + s_d2w[5]*u1);
            const float rd3 = r3 * fsig(s_d2b[3] + s_d2w[6]*u0 + s_d2w[7]*u1);

            const float wscale = fsig(s_rw[j]) * decay * 3.0f;
            w0 = fmaf(rd0, wscale, w0); w1 = fmaf(rd1, wscale, w1);
            w2 = fmaf(rd2, wscale, w2); w3 = fmaf(rd3, wscale, w3);

            if (j < 15) {
                fb0 = fmaf(rd0, 0.24f, fA0); fb1 = fmaf(rd1, 0.24f, fA1);
                fb2 = fmaf(rd2, 0.24f, fA2); fb3 = fmaf(rd3, 0.24f, fA3);
                __stcg(&g_fb[(j + 1) & 1][pbase + off],
                       make_float4(fb0, fb1, fb2, fb3));
            }
        }
        ys2p = ((int)(dly * 0.5f)) & 63;
        xs2p = ((int)dly)          & 63;
        decay *= 0.8f;
        if (j < 15) csync();
    }

    if (low) {
        float qh[4], kh[4];
        #pragma unroll
        for (int h = 0; h < 4; h++) {
            float q = s_aib[h], k = s_aib[4 + h], v = s_aib[8 + h];
            q = fmaf(s_aiw[h*4+0],     w0, q); q = fmaf(s_aiw[h*4+1],     w1, q);
            q = fmaf(s_aiw[h*4+2],     w2, q); q = fmaf(s_aiw[h*4+3],     w3, q);
            k = fmaf(s_aiw[(4+h)*4+0], w0, k); k = fmaf(s_aiw[(4+h)*4+1], w1, k);
            k = fmaf(s_aiw[(4+h)*4+2], w2, k); k = fmaf(s_aiw[(4+h)*4+3], w3, k);
            v = fmaf(s_aiw[(8+h)*4+0], w0, v); v = fmaf(s_aiw[(8+h)*4+1], w1, v);
            v = fmaf(s_aiw[(8+h)*4+2], w2, v); v = fmaf(s_aiw[(8+h)*4+3], w3, v);
            qh[h] = q; kh[h] = k;
            __stcg(&g_kv[((b*4 + h) << 12) + off], make_float2(k, v));
        }
        __stcg(&g_q4[pbase + off], make_float4(qh[0], qh[1], qh[2], qh[3]));
        float red[16];
        #pragma unroll
        for (int h = 0; h < 4; h++) {
            red[h] = qh[h]; red[4+h] = qh[h]; red[8+h] = kh[h]; red[12+h] = kh[h];
        }
        #pragma unroll
        for (int o = 16; o > 0; o >>= 1) {
            #pragma unroll
            for (int h = 0; h < 4; h++) {
                red[h]    = fminf(red[h],    __shfl_xor_sync(0xFFFFFFFFu, red[h],    o));
                red[4+h]  = fmaxf(red[4+h],  __shfl_xor_sync(0xFFFFFFFFu, red[4+h],  o));
                red[8+h]  = fminf(red[8+h],  __shfl_xor_sync(0xFFFFFFFFu, red[8+h],  o));
                red[12+h] = fmaxf(red[12+h], __shfl_xor_sync(0xFFFFFFFFu, red[12+h], o));
            }
        }
        if ((tid & 31) == 0) {
            #pragma unroll
            for (int i = 0; i < 16; i++) s_red[tid >> 5][i] = red[i];
        }
    }
    __syncthreads();
    if (tid < 16) {
        const bool ismax = (tid >> 2) & 1;
        float v = s_red[0][tid];
        #pragma unroll
        for (int wq = 1; wq < 16; wq++)
            v = ismax ? fmaxf(v, s_red[wq][tid]) : fminf(v, s_red[wq][tid]);
        g_red[b][rank][tid] = v;
    }
    csync();

    if (tid < 16) {
        const bool ismax = (tid >> 2) & 1;
        float v = __ldcg(&g_red[b][0][tid]);
        #pragma unroll
        for (int r = 1; r < 8; r++) {
            const float u = __ldcg(&g_red[b][r][tid]);
            v = ismax ? fmaxf(v, u) : fminf(v, u);
        }
        s_meta[tid] = v;
    }
    {
        const int head = rank >> 1;
        float4*       dst = (float4*)s_buf;
        const float4* src = (const float4*)&g_kv[((b*4 + head) << 12)];
        dst[tid]        = __ldcg(&src[tid]);
        dst[tid + 1024] = __ldcg(&src[tid + 1024]);
        __syncthreads();

        const float amin = s_meta[head],     amax = s_meta[4 + head];
        const float kmn  = s_meta[8 + head], kmx  = s_meta[12 + head];
        const float hs   = fmaxf((amax - amin) * (1.0f/60.0f), 1e-30f);
        const int   lane = tid & 31;
        const int   n    = ((rank & 1) << 5) + (tid >> 5);
        const float a2   = (amin + (float)(n - 1) * hs) * LOG2E;
        const float m2   = fmaxf(a2 * kmn, a2 * kmx);

        float num = 0.f, den = 0.f;
        const float2* p2 = (const float2*)s_buf;
        #pragma unroll 8
        for (int jj = 0; jj < 128; jj++) {
            const float2 kv = p2[lane + (jj << 5)];
            const float  e  = fexp2(fmaf(a2, kv.x, -m2));
            num = fmaf(e, kv.y, num);
            den += e;
        }
        #pragma unroll
        for (int o = 16; o > 0; o >>= 1) {
            num += __shfl_xor_sync(0xFFFFFFFFu, num, o);
            den += __shfl_xor_sync(0xFFFFFFFFu, den, o);
        }
        if (lane == 0)
            __stcg(&g_tab[(b*4 + head)*64 + n], __fdividef(num, den));
    }
    csync();

    if (tid < 256) s_buf[tid] = __ldcg(&g_tab[b*256 + tid]);
    __syncthreads();
    if (low) {
        const float4 q4 = __ldcg(&g_q4[pbase + off]);
        const float qa[4] = { q4.x, q4.y, q4.z, q4.w };
        float oh[4];
        #pragma unroll
        for (int h = 0; h < 4; h++) {
            const float amin = s_meta[h];
            const float hs   = fmaxf((s_meta[4+h] - amin) * (1.0f/60.0f), 1e-30f);
            float sr = (qa[h] - amin) * __fdividef(1.0f, hs);
            sr = fminf(fmaxf(sr, 0.0f), 60.0f);
            const float fi = floorf(sr);
            const int   i0 = (int)fi;
            const float f  = sr - fi;
            const float* t = &s_buf[(h << 6) + i0];
            const float fm1 = f + 1.0f, f1 = f - 1.0f, f2 = f - 2.0f;
            const float c0 = -f  * f1 * f2 * (1.0f/6.0f);
            const float c1 =  fm1 * f1 * f2 * 0.5f;
            const float c2 = -fm1 * f  * f2 * 0.5f;
            const float c3 =  fm1 * f  * f1 * (1.0f/6.0f);
            oh[h] = c0*t[0] + c1*t[1] + c2*t[2] + c3*t[3];
        }
        __stcg(&g_o4[pbase + off], make_float4(oh[0], oh[1], oh[2], oh[3]));
    }
    csync();

    if (low) {
        float sx = 0.f, sy = 0.f, sz = 0.f, sw = 0.f, cnt = 0.f;
        #pragma unroll
        for (int dy = -1; dy <= 1; dy++) {
            const int yy = y + dy;
            if ((unsigned)yy >= 64u) continue;
            #pragma unroll
            for (int dx = -1; dx <= 1; dx++) {
                const int xc = xx + dx;
                if ((unsigned)xc >= 64u) continue;
                const float4 o = __ldcg(&g_o4[pbase + (yy << 6) + xc]);
                sx += o.x; sy += o.y; sz += o.z; sw += o.w;
                cnt += 1.0f;
            }
        }
        float oc[4];
        #pragma unroll
        for (int c = 0; c < 4; c++) {
            float pr = cnt * s_aob[c];
            pr = fmaf(s_aow[c*4+0], sx, pr); pr = fmaf(s_aow[c*4+1], sy, pr);
            pr = fmaf(s_aow[c*4+2], sz, pr); pr = fmaf(s_aow[c*4+3], sw, pr);
            oc[c] = pr * (1.0f/9.0f);
        }
        __stcg(&g_w34[pbase + off], make_float4(oc[0], oc[1], oc[2], oc[3]));
    }
    csync();

    if (low) {
        const float4 ctr = __ldcg(&g_w34[pbase + off]);
        float n0 = 0.f, n1 = 0.f, n2 = 0.f, n3 = 0.f;
        float sf[8];
        float4 xctr = make_float4(0.f, 0.f, 0.f, 0.f);
        #pragma unroll
        for (int o = 0; o < 8; o++) sf[o] = s_spb[o];
        #pragma unroll
        for (int dy = -1; dy <= 1; dy++) {
            const int yy = y + dy;
            if ((unsigned)yy >= 64u) continue;
            #pragma unroll
            for (int dx = -1; dx <= 1; dx++) {
                const int xc = xx + dx;
                if ((unsigned)xc >= 64u) continue;
                const int s2 = (yy << 6) + xc;
                if (!(dy == 0 && dx == 0)) {
                    const float4 v = __ldcg(&g_w34[pbase + s2]);
                    n0 += v.x; n1 += v.y; n2 += v.z; n3 += v.w;
                }
                const float4 xv = __ldcg(&g_x4[pbase + s2]);
                if (dy == 0 && dx == 0) xctr = xv;
                const int wtap = (dy + 1)*3 + (dx + 1);
                #pragma unroll
                for (int o = 0; o < 8; o++) {
                    float a = sf[o];
                    a = fmaf(s_spw[(o*4 + 0)*9 + wtap], xv.x, a);
                    a = fmaf(s_spw[(o*4 + 1)*9 + wtap], xv.y, a);
                    a = fmaf(s_spw[(o*4 + 2)*9 + wtap], xv.z, a);
                    a = fmaf(s_spw[(o*4 + 3)*9 + wtap], xv.w, a);
                    sf[o] = a;
                }
            }
        }
        float wet4[4];
        wet4[0] = fmaf(8.0f*ctr.x - n0, 0.04f, ctr.x);
        wet4[1] = fmaf(8.0f*ctr.y - n1, 0.04f, ctr.y);
        wet4[2] = fmaf(8.0f*ctr.z - n2, 0.04f, ctr.z);
        wet4[3] = fmaf(8.0f*ctr.w - n3, 0.04f, ctr.w);

        const float xc4[4] = { xctr.x, xctr.y, xctr.z, xctr.w };
        #pragma unroll
        for (int c = 0; c < 4; c++) {
            float pr = s_ob[c];
            #pragma unroll
            for (int jq = 0; jq < 8; jq++) pr = fmaf(s_ow[c*12 + jq],     sf[jq],   pr);
            #pragma unroll
            for (int jq = 0; jq < 4; jq++) pr = fmaf(s_ow[c*12 + 8 + jq], wet4[jq], pr);
            out[((b*4 + c) << 12) + off] = fmaf(xc4[c], 0.7f, 0.3f * pr);
        }
    }
}

// ---------------- launcher ---------------------------------------------------
extern "C" void kernel_launch(void* const* d_in, const int* in_sizes, int n_in,
                              void* d_out, int out_size)
{
    const float* x   = (const float*)d_in[0];
    const float* rw  = (const float*)d_in[1];
    const float* rd  = (const float*)d_in[2];
    const float* spw = (const float*)d_in[4];
    const float* spb = (const float*)d_in[5];
    const float* fw  = (const float*)d_in[6];
    const float* fb  = (const float*)d_in[7];
    const float* d1w = (const float*)d_in[8];
    const float* d1b = (const float*)d_in[9];
    const float* d2w = (const float*)d_in[10];
    const float* d2b = (const float*)d_in[11];
    const float* aiw = (const float*)d_in[12];
    const float* aib = (const float*)d_in[13];
    const float* aow = (const float*)d_in[14];
    const float* aob = (const float*)d_in[15];
    const float* ow  = (const float*)d_in[16];
    const float* ob  = (const float*)d_in[17];
    float* out = (float*)d_out;

    // Try the cluster-16 (nonportable) config; fall back to proven cluster-8.
    bool use16 = false;
    if (cudaFuncSetAttribute(fused16,
            cudaFuncAttributeNonPortableClusterSizeAllowed, 1) == cudaSuccess) {
        cudaLaunchConfig_t qcfg = {};
        qcfg.gridDim  = dim3(16, 4, 1);
        qcfg.blockDim = dim3(512, 1, 1);
        qcfg.dynamicSmemBytes = 0;
        qcfg.stream = 0;
        int maxC = 0;
        if (cudaOccupancyMaxPotentialClusterSize(&maxC, fused16, &qcfg)
                == cudaSuccess && maxC >= 16)
            use16 = true;
    }
    cudaGetLastError();  // clear any sticky error from queries

    if (use16) {
        cudaLaunchConfig_t cfg = {};
        cfg.gridDim  = dim3(16, 4, 1);
        cfg.blockDim = dim3(512, 1, 1);
        cfg.dynamicSmemBytes = 0;
        cfg.stream = 0;
        cudaLaunchAttribute attrs[1];
        attrs[0].id = cudaLaunchAttributeClusterDimension;
        attrs[0].val.clusterDim = {16, 1, 1};
        cfg.attrs = attrs;
        cfg.numAttrs = 1;
        if (cudaLaunchKernelEx(&cfg, fused16, x, rw, rd, fw, fb,
                               d1w, d1b, d2w, d2b, aiw, aib, aow, aob,
                               spw, spb, ow, ob, out) == cudaSuccess)
            return;
        cudaGetLastError();  // clear and fall through to fallback
    }

    fused8<<<dim3(8, 4), 1024>>>(x, rw, rd, fw, fb, d1w, d1b, d2w, d2b,
                                 aiw, aib, aow, aob, spw, spb, ow, ob, out);
}